// round 2
// baseline (speedup 1.0000x reference)
#include <cuda_runtime.h>
#include <math.h>

#define BT 2
#define CC 128
#define HH 128
#define WW 128
#define HS 64           // downsampled H=W
#define NP 4096         // 64*64 patches / pixels
#define K1 1152         // C*9
#define QQ 2048         // C*16
#define HWF 16384       // 128*128
#define SCALEF 10.0f

// ---------------- scratch (static device allocations; no cudaMalloc) --------
__device__ float g_pn  [(size_t)BT*NP*K1];   // normalized 3x3 patches of b (down)
__device__ float g_fpat[(size_t)BT*NP*K1];   // 3x3 patches of f (down)
__device__ float g_raw [(size_t)BT*NP*QQ];   // 4x4 raw bg patches  [m][c*16+t]
__device__ float g_bufA[(size_t)BT*NP*NP];   // 128 MB ping
__device__ float g_bufB[(size_t)BT*NP*NP];   // 128 MB pong
__device__ float g_yblk[(size_t)BT*QQ*NP];   // GEMM2 out [q][p]
__device__ float g_y   [(size_t)BT*CC*HWF];  // attention output image
__device__ float g_h   [(size_t)BT*CC*HWF];  // hidden after conv1
__device__ float g_col [(size_t)BT*HWF*K1];  // im2col scratch
__device__ float g_eq  [NP];
__device__ float g_pmax[BT*32*NP];
__device__ float g_psum[BT*32*NP];
__device__ float g_cmax[BT*NP];
__device__ float g_csum[BT*NP];

// ---------------- patch builders -------------------------------------------
__global__ void k_pn(const float* __restrict__ bg) {
    int bn = blockIdx.x;             // b*NP + n
    int b = bn / NP, n = bn % NP;
    int ny = n / HS, nx = n % HS;
    int tid = threadIdx.x;
    float v[9];
    float ss = 0.f;
#pragma unroll
    for (int i = 0; i < 9; i++) {
        int k = tid + i * 128;                 // 0..1151
        int c = k / 9, kk = k % 9;
        int ki = kk / 3, kj = kk % 3;
        int y = ny + ki - 1, x = nx + kj - 1;
        float val = 0.f;
        if ((unsigned)y < HS && (unsigned)x < HS)
            val = bg[(((size_t)b*CC + c)*HH + 2*y)*WW + 2*x];
        v[i] = val;
        ss += val * val;
    }
    __shared__ float red[128];
    red[tid] = ss;
    __syncthreads();
    for (int s = 64; s > 0; s >>= 1) {
        if (tid < s) red[tid] += red[tid + s];
        __syncthreads();
    }
    float inv = 1.f / fmaxf(sqrtf(red[0]), 1e-4f);
    float* dst = g_pn + ((size_t)b*NP + n) * K1;
#pragma unroll
    for (int i = 0; i < 9; i++)
        dst[tid + i * 128] = v[i] * inv;
}

__global__ void k_fpat(const float* __restrict__ fg) {
    const int total = BT * NP * K1;
    for (int idx = blockIdx.x * blockDim.x + threadIdx.x; idx < total;
         idx += gridDim.x * blockDim.x) {
        int k = idx % K1; int t = idx / K1;
        int p = t % NP;   int b = t / NP;
        int c = k / 9, kk = k % 9, ki = kk / 3, kj = kk % 3;
        int py = p / HS, px = p % HS;
        int y = py + ki - 1, x = px + kj - 1;
        float v = 0.f;
        if ((unsigned)y < HS && (unsigned)x < HS)
            v = fg[(((size_t)b*CC + c)*HH + 2*y)*WW + 2*x];
        g_fpat[idx] = v;
    }
}

__global__ void k_raw(const float* __restrict__ bg) {
    const int total = BT * NP * QQ;
    for (int idx = blockIdx.x * blockDim.x + threadIdx.x; idx < total;
         idx += gridDim.x * blockDim.x) {
        int q = idx % QQ; int t = idx / QQ;
        int m = t % NP;   int b = t / NP;
        int c = q / 16, tt = q % 16, di = tt / 4, dj = tt % 4;
        int my = m / HS, mx = m % HS;
        int Y = 2*my + di - 1, X = 2*mx + dj - 1;
        float v = 0.f;
        if ((unsigned)Y < HH && (unsigned)X < WW)
            v = bg[(((size_t)b*CC + c)*HH + Y)*WW + X];
        g_raw[idx] = v;
    }
}

__global__ void k_eq(const float* __restrict__ mask) {
    int n = blockIdx.x * blockDim.x + threadIdx.x;
    if (n >= NP) return;
    int ny = n / HS, nx = n % HS;
    float s = 0.f;
#pragma unroll
    for (int i = 0; i < 3; i++)
#pragma unroll
        for (int j = 0; j < 3; j++) {
            int y = ny + i - 1, x = nx + j - 1;
            if ((unsigned)y < HS && (unsigned)x < HS)
                s += mask[(2*y)*WW + 2*x];
        }
    g_eq[n] = ((s / 9.f) == 0.f) ? 1.f : 0.f;
}

// ---------------- FP32 GEMMs ------------------------------------------------
// C[M][N] = sum_k A[m][k] * B[n][k]   (A: MxK row-major, B: NxK row-major)
// optional epilogue: +bias[row], ELU
__global__ void __launch_bounds__(256) gemm_nt(
    const float* __restrict__ A, const float* __restrict__ B, float* __restrict__ Cm,
    int M, int N, int K, const float* __restrict__ bias, int act)
{
    __shared__ float As[8][128];
    __shared__ float Bs[8][128];
    const int bm = blockIdx.y * 128;
    const int bn = blockIdx.x * 128;
    const int tid = threadIdx.x;
    const int tx = tid & 15, ty = tid >> 4;
    const int lr = tid >> 1, lc = (tid & 1) * 4;
    float acc[8][8];
#pragma unroll
    for (int i = 0; i < 8; i++)
#pragma unroll
        for (int j = 0; j < 8; j++) acc[i][j] = 0.f;

    for (int k0 = 0; k0 < K; k0 += 8) {
        float4 av = *(const float4*)(A + (size_t)(bm + lr) * K + k0 + lc);
        float4 bv = *(const float4*)(B + (size_t)(bn + lr) * K + k0 + lc);
        As[lc+0][lr] = av.x; As[lc+1][lr] = av.y; As[lc+2][lr] = av.z; As[lc+3][lr] = av.w;
        Bs[lc+0][lr] = bv.x; Bs[lc+1][lr] = bv.y; Bs[lc+2][lr] = bv.z; Bs[lc+3][lr] = bv.w;
        __syncthreads();
#pragma unroll
        for (int kk = 0; kk < 8; kk++) {
            float ar[8], br[8];
            *(float4*)(ar)   = *(const float4*)(&As[kk][ty*8]);
            *(float4*)(ar+4) = *(const float4*)(&As[kk][ty*8+4]);
            *(float4*)(br)   = *(const float4*)(&Bs[kk][tx*8]);
            *(float4*)(br+4) = *(const float4*)(&Bs[kk][tx*8+4]);
#pragma unroll
            for (int i = 0; i < 8; i++)
#pragma unroll
                for (int j = 0; j < 8; j++)
                    acc[i][j] = fmaf(ar[i], br[j], acc[i][j]);
        }
        __syncthreads();
    }
#pragma unroll
    for (int i = 0; i < 8; i++) {
        int row = bm + ty*8 + i;
        float bvv = bias ? bias[row] : 0.f;
#pragma unroll
        for (int j = 0; j < 8; j++) {
            float v = acc[i][j] + bvv;
            if (act) v = v > 0.f ? v : (expf(v) - 1.f);
            Cm[(size_t)row * N + bn + tx*8 + j] = v;
        }
    }
}

// C[M][N] = sum_k A[k][m] * B[k][n]  (A: KxM row-major, B: KxN row-major)
__global__ void __launch_bounds__(256) gemm_tn(
    const float* __restrict__ A, const float* __restrict__ B, float* __restrict__ Cm,
    int M, int N, int K)
{
    __shared__ float As[8][128];
    __shared__ float Bs[8][128];
    const int bm = blockIdx.y * 128;
    const int bn = blockIdx.x * 128;
    const int tid = threadIdx.x;
    const int tx = tid & 15, ty = tid >> 4;
    const int kk = tid >> 5, c4 = (tid & 31) * 4;
    float acc[8][8];
#pragma unroll
    for (int i = 0; i < 8; i++)
#pragma unroll
        for (int j = 0; j < 8; j++) acc[i][j] = 0.f;

    for (int k0 = 0; k0 < K; k0 += 8) {
        *(float4*)(&As[kk][c4]) = *(const float4*)(A + (size_t)(k0 + kk) * M + bm + c4);
        *(float4*)(&Bs[kk][c4]) = *(const float4*)(B + (size_t)(k0 + kk) * N + bn + c4);
        __syncthreads();
#pragma unroll
        for (int k2 = 0; k2 < 8; k2++) {
            float ar[8], br[8];
            *(float4*)(ar)   = *(const float4*)(&As[k2][ty*8]);
            *(float4*)(ar+4) = *(const float4*)(&As[k2][ty*8+4]);
            *(float4*)(br)   = *(const float4*)(&Bs[k2][tx*8]);
            *(float4*)(br+4) = *(const float4*)(&Bs[k2][tx*8+4]);
#pragma unroll
            for (int i = 0; i < 8; i++)
#pragma unroll
                for (int j = 0; j < 8; j++)
                    acc[i][j] = fmaf(ar[i], br[j], acc[i][j]);
        }
        __syncthreads();
    }
#pragma unroll
    for (int i = 0; i < 8; i++) {
        int row = bm + ty*8 + i;
#pragma unroll
        for (int j = 0; j < 8; j++)
            Cm[(size_t)row * N + bn + tx*8 + j] = acc[i][j];
    }
}

// ---------------- fuse / permute / softmax ----------------------------------
__global__ void k_fuse(const float* __restrict__ in, float* __restrict__ out) {
    const size_t total = (size_t)BT * NP * NP;
    const size_t stride = (size_t)gridDim.x * blockDim.x;
    for (size_t idx = (size_t)blockIdx.x * blockDim.x + threadIdx.x; idx < total; idx += stride) {
        int c = (int)(idx % NP);
        size_t t = idx / NP;
        int r = (int)(t % NP);
        int b = (int)(t / NP);
        const float* base = in + (size_t)b * NP * NP;
        float s = base[(size_t)r * NP + c];
        if (r > 0 && c > 0)            s += base[(size_t)(r-1) * NP + (c-1)];
        if (r < NP-1 && c < NP-1)      s += base[(size_t)(r+1) * NP + (c+1)];
        out[idx] = s;
    }
}

// out[(nx*64+ny)][(px*64+py)] = in[(ny*64+nx)][(py*64+px)]
__global__ void k_perm(const float* __restrict__ in, float* __restrict__ out) {
    __shared__ float tile[64 * 65];
    int brow = blockIdx.x;                    // b*NP + r'
    int b = brow / NP, rp = brow % NP;
    int nx = rp >> 6, ny = rp & 63;
    int r = ny * 64 + nx;
    const float* src = in  + ((size_t)b * NP + r ) * NP;
    float*       dst = out + ((size_t)b * NP + rp) * NP;
    int tid = threadIdx.x;
    for (int k = tid; k < NP; k += 256)
        tile[(k & 63) * 65 + (k >> 6)] = src[k];
    __syncthreads();
    for (int j = tid; j < NP; j += 256)
        dst[j] = tile[(j >> 6) * 65 + (j & 63)];
}

__global__ void k_smax1(const float* __restrict__ in) {
    int col = blockIdx.x * 256 + threadIdx.x;     // 0..4095
    int chunk = blockIdx.y;                        // 0..31
    int b = blockIdx.z;
    const float* base = in + (size_t)b * NP * NP;
    float mx = -1e30f, sm = 0.f;
    int r0 = chunk * 128;
    for (int r = r0; r < r0 + 128; r++) {
        float l = base[(size_t)r * NP + col] * (g_eq[r] * SCALEF);
        if (l > mx) { sm = sm * expf(mx - l) + 1.f; mx = l; }
        else        { sm += expf(l - mx); }
    }
    g_pmax[((size_t)b * 32 + chunk) * NP + col] = mx;
    g_psum[((size_t)b * 32 + chunk) * NP + col] = sm;
}

__global__ void k_smax2() {
    int idx = blockIdx.x * blockDim.x + threadIdx.x;   // b*NP + col
    if (idx >= BT * NP) return;
    int b = idx / NP, col = idx % NP;
    float M = -1e30f;
    for (int i = 0; i < 32; i++)
        M = fmaxf(M, g_pmax[((size_t)b * 32 + i) * NP + col]);
    float S = 0.f;
    for (int i = 0; i < 32; i++)
        S += g_psum[((size_t)b * 32 + i) * NP + col] *
             expf(g_pmax[((size_t)b * 32 + i) * NP + col] - M);
    g_cmax[idx] = M;
    g_csum[idx] = S;
}

__global__ void k_smax3(const float* __restrict__ in, float* __restrict__ out) {
    const size_t total = (size_t)BT * NP * NP;
    const size_t stride = (size_t)gridDim.x * blockDim.x;
    for (size_t idx = (size_t)blockIdx.x * blockDim.x + threadIdx.x; idx < total; idx += stride) {
        int c = (int)(idx % NP);
        size_t t = idx / NP;
        int r = (int)(t % NP);
        int b = (int)(t / NP);
        float eq = g_eq[r];
        float l = in[idx] * (eq * SCALEF);
        out[idx] = expf(l - g_cmax[b * NP + c]) / g_csum[b * NP + c] * eq;
    }
}

// ---------------- transposed-conv gather + im2col ---------------------------
__global__ void k_gather() {
    const int total = BT * CC * HWF;
    for (int idx = blockIdx.x * blockDim.x + threadIdx.x; idx < total;
         idx += gridDim.x * blockDim.x) {
        int X = idx & 127;
        int t = idx >> 7;
        int Y = t & 127; t >>= 7;
        int c = t & 127;
        int b = t >> 7;
        float acc = 0.f;
#pragma unroll
        for (int ki = 0; ki < 4; ki++) {
            int tyy = Y + 1 - ki;
            if (tyy < 0 || (tyy & 1)) continue;
            int yq = tyy >> 1;
            if (yq >= HS) continue;
#pragma unroll
            for (int kj = 0; kj < 4; kj++) {
                int txx = X + 1 - kj;
                if (txx < 0 || (txx & 1)) continue;
                int xq = txx >> 1;
                if (xq >= HS) continue;
                acc += g_yblk[((size_t)b * QQ + c * 16 + ki * 4 + kj) * NP + yq * HS + xq];
            }
        }
        g_y[idx] = acc * 0.25f;
    }
}

__global__ void k_im2col(const float* __restrict__ src) {
    const size_t total = (size_t)BT * HWF * K1;
    const size_t stride = (size_t)gridDim.x * blockDim.x;
    for (size_t idx = (size_t)blockIdx.x * blockDim.x + threadIdx.x; idx < total; idx += stride) {
        int k = (int)(idx % K1);
        size_t t = idx / K1;
        int p = (int)(t % HWF);
        int b = (int)(t / HWF);
        int c = k / 9, kk = k % 9, ki = kk / 3, kj = kk % 3;
        int Y = p >> 7, X = p & 127;
        int y = Y + ki - 1, x = X + kj - 1;
        float v = 0.f;
        if ((unsigned)y < HH && (unsigned)x < WW)
            v = src[(((size_t)b * CC + c) * HH + y) * WW + x];
        g_col[idx] = v;
    }
}

// ---------------- host orchestration ----------------------------------------
extern "C" void kernel_launch(void* const* d_in, const int* in_sizes, int n_in,
                              void* d_out, int out_size) {
    const float* fg   = (const float*)d_in[0];
    const float* bg   = (const float*)d_in[1];
    const float* mask = (const float*)d_in[2];
    const float* w1   = (const float*)d_in[3];
    const float* b1   = (const float*)d_in[4];
    const float* w2   = (const float*)d_in[5];
    const float* b2   = (const float*)d_in[6];
    float* out = (float*)d_out;

    float *pn, *fpat, *raw, *bufA, *bufB, *yblk, *yb, *hb, *col;
    cudaGetSymbolAddress((void**)&pn,   g_pn);
    cudaGetSymbolAddress((void**)&fpat, g_fpat);
    cudaGetSymbolAddress((void**)&raw,  g_raw);
    cudaGetSymbolAddress((void**)&bufA, g_bufA);
    cudaGetSymbolAddress((void**)&bufB, g_bufB);
    cudaGetSymbolAddress((void**)&yblk, g_yblk);
    cudaGetSymbolAddress((void**)&yb,   g_y);
    cudaGetSymbolAddress((void**)&hb,   g_h);
    cudaGetSymbolAddress((void**)&col,  g_col);

    k_pn  <<<BT * NP, 128>>>(bg);
    k_fpat<<<4096, 256>>>(fg);
    k_raw <<<8192, 256>>>(bg);
    k_eq  <<<16, 256>>>(mask);

    // GEMM1: s0[n][p] = pn . fpat^T
    for (int b = 0; b < BT; b++)
        gemm_nt<<<dim3(32, 32), 256>>>(pn + (size_t)b*NP*K1, fpat + (size_t)b*NP*K1,
                                       bufA + (size_t)b*NP*NP, NP, NP, K1, nullptr, 0);

    k_fuse<<<16384, 256>>>(bufA, bufB);        // fuse 1
    k_perm<<<BT * NP, 256>>>(bufB, bufA);      // 4D permutation
    k_fuse<<<16384, 256>>>(bufA, bufB);        // fuse 2

    k_smax1<<<dim3(16, 32, BT), 256>>>(bufB);
    k_smax2<<<32, 256>>>();
    k_smax3<<<16384, 256>>>(bufB, bufA);       // s_soft -> bufA

    // GEMM2: yblk[q][p] = sum_m raw[m][q] * s_soft[m][p]
    for (int b = 0; b < BT; b++)
        gemm_tn<<<dim3(32, 16), 256>>>(raw + (size_t)b*NP*QQ, bufA + (size_t)b*NP*NP,
                                       yblk + (size_t)b*QQ*NP, QQ, NP, NP);

    k_gather<<<4096, 256>>>();                 // transposed-conv scatter -> g_y

    // conv1 + ELU
    k_im2col<<<16384, 256>>>(yb);
    for (int b = 0; b < BT; b++)
        gemm_nt<<<dim3(HWF / 128, 1), 256>>>(w1, col + (size_t)b*HWF*K1,
                                             hb + (size_t)b*CC*HWF, CC, HWF, K1, b1, 1);
    // conv2 + ELU
    k_im2col<<<16384, 256>>>(hb);
    for (int b = 0; b < BT; b++)
        gemm_nt<<<dim3(HWF / 128, 1), 256>>>(w2, col + (size_t)b*HWF*K1,
                                             out + (size_t)b*CC*HWF, CC, HWF, K1, b2, 1);
}

// round 4
// speedup vs baseline: 2.7047x; 2.7047x over previous
#include <cuda_runtime.h>
#include <cuda_bf16.h>
#include <math.h>
#include <stdint.h>

#define BT 2
#define CC 128
#define HH 128
#define WW 128
#define HS 64           // downsampled H=W
#define NP 4096         // 64*64 patches / pixels
#define K1 1152         // C*9
#define QQ 2048         // C*16
#define HWF 16384       // 128*128
#define SCALEF 10.0f

// ===================== scratch (static device, no cudaMalloc) ===============
__device__ __align__(256) __nv_bfloat16 g_pn_h [(size_t)BT*NP*K1];
__device__ __align__(256) __nv_bfloat16 g_pn_l [(size_t)BT*NP*K1];
__device__ __align__(256) __nv_bfloat16 g_fp_h [(size_t)BT*NP*K1];
__device__ __align__(256) __nv_bfloat16 g_fp_l [(size_t)BT*NP*K1];
__device__ __align__(256) __nv_bfloat16 g_rt_h [(size_t)BT*QQ*NP];   // raw patches T [q][m]
__device__ __align__(256) __nv_bfloat16 g_rt_l [(size_t)BT*QQ*NP];
__device__ __align__(256) __nv_bfloat16 g_sT_h [(size_t)BT*NP*NP];   // softmax T [p][m]
__device__ __align__(256) __nv_bfloat16 g_sT_l [(size_t)BT*NP*NP];
__device__ __align__(256) __nv_bfloat16 g_col_h[(size_t)BT*HWF*K1];  // im2col bf16
__device__ __align__(256) __nv_bfloat16 g_col_l[(size_t)BT*HWF*K1];
__device__ __align__(256) __nv_bfloat16 g_w1h[CC*K1], g_w1l[CC*K1], g_w2h[CC*K1], g_w2l[CC*K1];
__device__ float g_bufA[(size_t)BT*NP*NP];
__device__ float g_bufB[(size_t)BT*NP*NP];
__device__ float g_yblk[(size_t)BT*QQ*NP];
__device__ float g_y   [(size_t)BT*CC*HWF];
__device__ float g_h   [(size_t)BT*CC*HWF];
__device__ float g_eq  [NP];
__device__ float g_pmax[BT*32*NP];
__device__ float g_psum[BT*32*NP];
__device__ float g_cmax[BT*NP];
__device__ float g_csum[BT*NP];

__device__ __forceinline__ void split_store(__nv_bfloat16* H, __nv_bfloat16* L,
                                            size_t idx, float v) {
    __nv_bfloat16 h = __float2bfloat16(v);
    H[idx] = h;
    L[idx] = __float2bfloat16(v - __bfloat162float(h));
}

__device__ __forceinline__ uint32_t smem_u32(const void* p) {
    uint32_t a;
    asm("{ .reg .u64 t; cvta.to.shared.u64 t, %1; cvt.u32.u64 %0, t; }" : "=r"(a) : "l"(p));
    return a;
}
__device__ __forceinline__ void ldsm_x4(uint32_t (&r)[4], uint32_t addr) {
    asm volatile("ldmatrix.sync.aligned.m8n8.x4.shared.b16 {%0,%1,%2,%3}, [%4];"
                 : "=r"(r[0]), "=r"(r[1]), "=r"(r[2]), "=r"(r[3]) : "r"(addr));
}
__device__ __forceinline__ void mma16816(float (&d)[4], const uint32_t (&a)[4],
                                         uint32_t b0, uint32_t b1) {
    asm volatile("mma.sync.aligned.m16n8k16.row.col.f32.bf16.bf16.f32 "
        "{%0,%1,%2,%3}, {%4,%5,%6,%7}, {%8,%9}, {%0,%1,%2,%3};"
        : "+f"(d[0]), "+f"(d[1]), "+f"(d[2]), "+f"(d[3])
        : "r"(a[0]), "r"(a[1]), "r"(a[2]), "r"(a[3]), "r"(b0), "r"(b1));
}
__device__ __forceinline__ void cpasync16(uint32_t saddr, const void* g) {
    asm volatile("cp.async.cg.shared.global [%0], [%1], 16;" :: "r"(saddr), "l"(g));
}

// ===================== patch builders =====================
__global__ void k_pn(const float* __restrict__ bg) {
    int bn = blockIdx.x;
    int b = bn / NP, n = bn % NP;
    int ny = n / HS, nx = n % HS;
    int tid = threadIdx.x;
    float v[9];
    float ss = 0.f;
#pragma unroll
    for (int i = 0; i < 9; i++) {
        int k = tid + i * 128;
        int c = k / 9, kk = k % 9;
        int ki = kk / 3, kj = kk % 3;
        int y = ny + ki - 1, x = nx + kj - 1;
        float val = 0.f;
        if ((unsigned)y < HS && (unsigned)x < HS)
            val = bg[(((size_t)b*CC + c)*HH + 2*y)*WW + 2*x];
        v[i] = val;
        ss += val * val;
    }
    __shared__ float red[128];
    red[tid] = ss;
    __syncthreads();
    for (int s = 64; s > 0; s >>= 1) {
        if (tid < s) red[tid] += red[tid + s];
        __syncthreads();
    }
    float inv = 1.f / fmaxf(sqrtf(red[0]), 1e-4f);
    size_t base = ((size_t)b*NP + n) * K1;
#pragma unroll
    for (int i = 0; i < 9; i++)
        split_store(g_pn_h, g_pn_l, base + tid + i*128, v[i] * inv);
}

__global__ void k_fpat(const float* __restrict__ fg) {
    const int total = BT * NP * K1;
    for (int idx = blockIdx.x * blockDim.x + threadIdx.x; idx < total;
         idx += gridDim.x * blockDim.x) {
        int k = idx % K1; int t = idx / K1;
        int p = t % NP;   int b = t / NP;
        int c = k / 9, kk = k % 9, ki = kk / 3, kj = kk % 3;
        int py = p / HS, px = p % HS;
        int y = py + ki - 1, x = px + kj - 1;
        float v = 0.f;
        if ((unsigned)y < HS && (unsigned)x < HS)
            v = fg[(((size_t)b*CC + c)*HH + 2*y)*WW + 2*x];
        split_store(g_fp_h, g_fp_l, (size_t)idx, v);
    }
}

__global__ void k_rawT(const float* __restrict__ bg) {
    const size_t total = (size_t)BT * QQ * NP;
    const size_t stride = (size_t)gridDim.x * blockDim.x;
    for (size_t idx = (size_t)blockIdx.x * blockDim.x + threadIdx.x; idx < total; idx += stride) {
        int m = (int)(idx % NP);
        size_t t = idx / NP;
        int q = (int)(t % QQ);
        int b = (int)(t / QQ);
        int c = q >> 4, tt = q & 15, di = tt >> 2, dj = tt & 3;
        int my = m / HS, mx = m % HS;
        int Y = 2*my + di - 1, X = 2*mx + dj - 1;
        float v = 0.f;
        if ((unsigned)Y < HH && (unsigned)X < WW)
            v = bg[(((size_t)b*CC + c)*HH + Y)*WW + X];
        split_store(g_rt_h, g_rt_l, idx, v);
    }
}

__global__ void k_eq(const float* __restrict__ mask) {
    int n = blockIdx.x * blockDim.x + threadIdx.x;
    if (n >= NP) return;
    int ny = n / HS, nx = n % HS;
    float s = 0.f;
#pragma unroll
    for (int i = 0; i < 3; i++)
#pragma unroll
        for (int j = 0; j < 3; j++) {
            int y = ny + i - 1, x = nx + j - 1;
            if ((unsigned)y < HS && (unsigned)x < HS)
                s += mask[(2*y)*WW + 2*x];
        }
    g_eq[n] = ((s / 9.f) == 0.f) ? 1.f : 0.f;
}

__global__ void k_wsplit(const float* __restrict__ w, __nv_bfloat16* H, __nv_bfloat16* L) {
    int idx = blockIdx.x * blockDim.x + threadIdx.x;
    if (idx >= CC * K1) return;
    split_store(H, L, (size_t)idx, w[idx]);
}

// ===================== mma.sync bf16-split GEMM =====================
// C[128m x 128n per block] = sum_k (Ah+Al)[m][k]*(Bh+Bl)[n][k], fp32 accum.
// A,B row-major K-contiguous. K % 32 == 0. batch via blockIdx.z strides.
#define KT 32
#define STAGES 3
#define STAGE_BYTES (4*128*KT*2)           // 32768
#define MGEMM_SMEM (STAGES*STAGE_BYTES)    // 98304

__global__ void __launch_bounds__(256, 1) mgemm(
    const __nv_bfloat16* __restrict__ Ah, const __nv_bfloat16* __restrict__ Al,
    const __nv_bfloat16* __restrict__ Bh, const __nv_bfloat16* __restrict__ Bl,
    float* __restrict__ C, int K, int N,
    size_t sA, size_t sB, size_t sC,
    const float* __restrict__ bias, int act)
{
    extern __shared__ char sm[];
    const uint32_t smb = smem_u32(sm);
    const int tid = threadIdx.x;
    const int bz = blockIdx.z;
    const int bm = blockIdx.y * 128;
    const int bn = blockIdx.x * 128;
    C += sC * bz;

    // loader role: tensor j = tid/64 (0:Ah 1:Al 2:Bh 3:Bl)
    const int j   = tid >> 6;
    const int l64 = tid & 63;
    const int rbase = (j < 2) ? bm : bn;
    const __nv_bfloat16* src =
        (j == 0) ? Ah + sA*bz : (j == 1) ? Al + sA*bz : (j == 2) ? Bh + sB*bz : Bl + sB*bz;

    const int NC = K >> 5;   // 32-wide K chunks (NC >= 3 for all our shapes)

    // prologue: stages 0..STAGES-2
#pragma unroll
    for (int s = 0; s < STAGES - 1; s++) {
        const int kc = s * KT;
#pragma unroll
        for (int i = 0; i < 8; i++) {
            int id = l64 + i * 64;
            int row = id >> 2, ch = id & 3;
            const void* g = src + (size_t)(rbase + row) * K + kc + ch * 8;
            uint32_t sa = smb + s*STAGE_BYTES + j*8192 + row*64 + ((ch ^ ((row >> 1) & 3)) << 4);
            cpasync16(sa, g);
        }
        asm volatile("cp.async.commit_group;");
    }

    const int wid = tid >> 5, lane = tid & 31;
    const int wm = wid & 1, wn = wid >> 1;

    float acc[4][4][4];
#pragma unroll
    for (int a = 0; a < 4; a++)
#pragma unroll
        for (int bb = 0; bb < 4; bb++)
#pragma unroll
            for (int c = 0; c < 4; c++) acc[a][bb][c] = 0.f;

    for (int i = 0; i < NC; i++) {
        asm volatile("cp.async.wait_group 1;");
        __syncthreads();

        // issue loads for stage i+2
        if (i + STAGES - 1 < NC) {
            const int s2 = (i + STAGES - 1) % STAGES;
            const int kc = (i + STAGES - 1) * KT;
#pragma unroll
            for (int it = 0; it < 8; it++) {
                int id = l64 + it * 64;
                int row = id >> 2, ch = id & 3;
                const void* g = src + (size_t)(rbase + row) * K + kc + ch * 8;
                uint32_t sa = smb + s2*STAGE_BYTES + j*8192 + row*64 + ((ch ^ ((row >> 1) & 3)) << 4);
                cpasync16(sa, g);
            }
        }
        asm volatile("cp.async.commit_group;");

        // compute stage i%3 : two k16 halves
        const uint32_t stb = smb + (i % STAGES) * STAGE_BYTES;
#pragma unroll
        for (int h = 0; h < 2; h++) {
            uint32_t ah[4][4], al[4][4];
            uint32_t bh[4][2], bl[4][2];
#pragma unroll
            for (int tm = 0; tm < 4; tm++) {
                int row = wm*64 + tm*16 + (lane & 15);
                int ch  = 2*h + (lane >> 4);
                uint32_t ad = stb + row*64 + ((ch ^ ((row >> 1) & 3)) << 4);
                ldsm_x4(ah[tm], ad);
                ldsm_x4(al[tm], ad + 8192);
            }
#pragma unroll
            for (int tp = 0; tp < 2; tp++) {
                int row = wn*32 + tp*16 + ((lane >> 4) << 3) + (lane & 7);
                int ch  = 2*h + ((lane >> 3) & 1);
                uint32_t bd = stb + 16384 + row*64 + ((ch ^ ((row >> 1) & 3)) << 4);
                uint32_t r[4];
                ldsm_x4(r, bd);
                bh[tp*2][0] = r[0]; bh[tp*2][1] = r[1];
                bh[tp*2+1][0] = r[2]; bh[tp*2+1][1] = r[3];
                ldsm_x4(r, bd + 8192);
                bl[tp*2][0] = r[0]; bl[tp*2][1] = r[1];
                bl[tp*2+1][0] = r[2]; bl[tp*2+1][1] = r[3];
            }
#pragma unroll
            for (int tm = 0; tm < 4; tm++)
#pragma unroll
                for (int tn = 0; tn < 4; tn++) {
                    mma16816(acc[tm][tn], ah[tm], bh[tn][0], bh[tn][1]);
                    mma16816(acc[tm][tn], ah[tm], bl[tn][0], bl[tn][1]);
                    mma16816(acc[tm][tn], al[tm], bh[tn][0], bh[tn][1]);
                }
        }
    }

    // epilogue: c0,c1 -> (row, 2c..2c+1), c2,c3 -> (row+8, same cols)
#pragma unroll
    for (int tm = 0; tm < 4; tm++) {
        int row = bm + wm*64 + tm*16 + (lane >> 2);
#pragma unroll
        for (int hf = 0; hf < 2; hf++) {
            int r = row + hf*8;
            float bv = bias ? bias[r] : 0.f;
            float* dst = C + (size_t)r * N + bn + wn*32 + (lane & 3)*2;
#pragma unroll
            for (int tn = 0; tn < 4; tn++) {
                float x0 = acc[tm][tn][hf*2+0] + bv;
                float x1 = acc[tm][tn][hf*2+1] + bv;
                if (act) {
                    x0 = x0 > 0.f ? x0 : expf(x0) - 1.f;
                    x1 = x1 > 0.f ? x1 : expf(x1) - 1.f;
                }
                *(float2*)(dst + tn*8) = make_float2(x0, x1);
            }
        }
    }
}

// ===================== fuse / permute / softmax =====================
__global__ void k_fuse(const float* __restrict__ in, float* __restrict__ out) {
    const size_t total = (size_t)BT * NP * NP;
    const size_t stride = (size_t)gridDim.x * blockDim.x;
    for (size_t idx = (size_t)blockIdx.x * blockDim.x + threadIdx.x; idx < total; idx += stride) {
        int c = (int)(idx % NP);
        size_t t = idx / NP;
        int r = (int)(t % NP);
        int b = (int)(t / NP);
        const float* base = in + (size_t)b * NP * NP;
        float s = base[(size_t)r * NP + c];
        if (r > 0 && c > 0)            s += base[(size_t)(r-1) * NP + (c-1)];
        if (r < NP-1 && c < NP-1)      s += base[(size_t)(r+1) * NP + (c+1)];
        out[idx] = s;
    }
}

__global__ void k_perm(const float* __restrict__ in, float* __restrict__ out) {
    __shared__ float tile[64 * 65];
    int brow = blockIdx.x;
    int b = brow / NP, rp = brow % NP;
    int nx = rp >> 6, ny = rp & 63;
    int r = ny * 64 + nx;
    const float* src = in  + ((size_t)b * NP + r ) * NP;
    float*       dst = out + ((size_t)b * NP + rp) * NP;
    int tid = threadIdx.x;
    for (int k = tid; k < NP; k += 256)
        tile[(k & 63) * 65 + (k >> 6)] = src[k];
    __syncthreads();
    for (int j = tid; j < NP; j += 256)
        dst[j] = tile[(j >> 6) * 65 + (j & 63)];
}

__global__ void k_smax1(const float* __restrict__ in) {
    int col = blockIdx.x * 256 + threadIdx.x;
    int chunk = blockIdx.y;
    int b = blockIdx.z;
    const float* base = in + (size_t)b * NP * NP;
    float mx = -1e30f, sm = 0.f;
    int r0 = chunk * 128;
    for (int r = r0; r < r0 + 128; r++) {
        float l = base[(size_t)r * NP + col] * (g_eq[r] * SCALEF);
        if (l > mx) { sm = sm * expf(mx - l) + 1.f; mx = l; }
        else        { sm += expf(l - mx); }
    }
    g_pmax[((size_t)b * 32 + chunk) * NP + col] = mx;
    g_psum[((size_t)b * 32 + chunk) * NP + col] = sm;
}

__global__ void k_smax2() {
    int idx = blockIdx.x * blockDim.x + threadIdx.x;
    if (idx >= BT * NP) return;
    int b = idx / NP, col = idx % NP;
    float M = -1e30f;
    for (int i = 0; i < 32; i++)
        M = fmaxf(M, g_pmax[((size_t)b * 32 + i) * NP + col]);
    float S = 0.f;
    for (int i = 0; i < 32; i++)
        S += g_psum[((size_t)b * 32 + i) * NP + col] *
             expf(g_pmax[((size_t)b * 32 + i) * NP + col] - M);
    g_cmax[idx] = M;
    g_csum[idx] = S;
}

// softmax + transpose: sT[p][m] bf16 hi/lo
__global__ void k_smax3T(const float* __restrict__ in) {
    __shared__ float tile[32][33];
    int b = blockIdx.z;
    int r0 = blockIdx.y * 32;   // m
    int c0 = blockIdx.x * 32;   // p
    int tx = threadIdx.x & 31, ty = threadIdx.x >> 5;
    const float* base = in + (size_t)b * NP * NP;
#pragma unroll
    for (int k = 0; k < 4; k++) {
        int r = r0 + ty + k * 8;
        int c = c0 + tx;
        float eq = g_eq[r];
        float l = base[(size_t)r * NP + c] * (eq * SCALEF);
        tile[ty + k*8][tx] = expf(l - g_cmax[b * NP + c]) / g_csum[b * NP + c] * eq;
    }
    __syncthreads();
#pragma unroll
    for (int k = 0; k < 4; k++) {
        int p = c0 + ty + k * 8;
        int m = r0 + tx;
        float v = tile[tx][ty + k*8];
        split_store(g_sT_h, g_sT_l, ((size_t)b * NP + p) * NP + m, v);
    }
}

// ===================== transposed-conv gather + im2col =====================
__global__ void k_gather() {
    const int total = BT * CC * HWF;
    for (int idx = blockIdx.x * blockDim.x + threadIdx.x; idx < total;
         idx += gridDim.x * blockDim.x) {
        int X = idx & 127;
        int t = idx >> 7;
        int Y = t & 127; t >>= 7;
        int c = t & 127;
        int b = t >> 7;
        float acc = 0.f;
#pragma unroll
        for (int ki = 0; ki < 4; ki++) {
            int tyy = Y + 1 - ki;
            if (tyy < 0 || (tyy & 1)) continue;
            int yq = tyy >> 1;
            if (yq >= HS) continue;
#pragma unroll
            for (int kj = 0; kj < 4; kj++) {
                int txx = X + 1 - kj;
                if (txx < 0 || (txx & 1)) continue;
                int xq = txx >> 1;
                if (xq >= HS) continue;
                acc += g_yblk[((size_t)b * QQ + c * 16 + ki * 4 + kj) * NP + yq * HS + xq];
            }
        }
        g_y[idx] = acc * 0.25f;
    }
}

__global__ void k_im2colB(const float* __restrict__ src) {
    const size_t total = (size_t)BT * HWF * K1;
    const size_t stride = (size_t)gridDim.x * blockDim.x;
    for (size_t idx = (size_t)blockIdx.x * blockDim.x + threadIdx.x; idx < total; idx += stride) {
        int k = (int)(idx % K1);
        size_t t = idx / K1;
        int p = (int)(t % HWF);
        int b = (int)(t / HWF);
        int c = k / 9, kk = k % 9, ki = kk / 3, kj = kk % 3;
        int Y = p >> 7, X = p & 127;
        int y = Y + ki - 1, x = X + kj - 1;
        float v = 0.f;
        if ((unsigned)y < HH && (unsigned)x < WW)
            v = src[(((size_t)b * CC + c) * HH + y) * WW + x];
        split_store(g_col_h, g_col_l, idx, v);
    }
}

// ===================== host orchestration =====================
extern "C" void kernel_launch(void* const* d_in, const int* in_sizes, int n_in,
                              void* d_out, int out_size) {
    const float* fg   = (const float*)d_in[0];
    const float* bg   = (const float*)d_in[1];
    const float* mask = (const float*)d_in[2];
    const float* w1   = (const float*)d_in[3];
    const float* b1   = (const float*)d_in[4];
    const float* w2   = (const float*)d_in[5];
    const float* b2   = (const float*)d_in[6];
    float* out = (float*)d_out;

    cudaFuncSetAttribute(mgemm, cudaFuncAttributeMaxDynamicSharedMemorySize, MGEMM_SMEM);

    __nv_bfloat16 *pnh, *pnl, *fph, *fpl, *rth, *rtl, *sth, *stl, *colh, *coll;
    __nv_bfloat16 *w1h, *w1l, *w2h, *w2l;
    float *bufA, *bufB, *yblk, *yb, *hb;
    cudaGetSymbolAddress((void**)&pnh, g_pn_h);  cudaGetSymbolAddress((void**)&pnl, g_pn_l);
    cudaGetSymbolAddress((void**)&fph, g_fp_h);  cudaGetSymbolAddress((void**)&fpl, g_fp_l);
    cudaGetSymbolAddress((void**)&rth, g_rt_h);  cudaGetSymbolAddress((void**)&rtl, g_rt_l);
    cudaGetSymbolAddress((void**)&sth, g_sT_h);  cudaGetSymbolAddress((void**)&stl, g_sT_l);
    cudaGetSymbolAddress((void**)&colh, g_col_h); cudaGetSymbolAddress((void**)&coll, g_col_l);
    cudaGetSymbolAddress((void**)&w1h, g_w1h);   cudaGetSymbolAddress((void**)&w1l, g_w1l);
    cudaGetSymbolAddress((void**)&w2h, g_w2h);   cudaGetSymbolAddress((void**)&w2l, g_w2l);
    cudaGetSymbolAddress((void**)&bufA, g_bufA);
    cudaGetSymbolAddress((void**)&bufB, g_bufB);
    cudaGetSymbolAddress((void**)&yblk, g_yblk);
    cudaGetSymbolAddress((void**)&yb,   g_y);
    cudaGetSymbolAddress((void**)&hb,   g_h);

    // prep
    k_pn    <<<BT * NP, 128>>>(bg);
    k_fpat  <<<4096, 256>>>(fg);
    k_rawT  <<<8192, 256>>>(bg);
    k_eq    <<<16, 256>>>(mask);
    k_wsplit<<<(CC*K1 + 255)/256, 256>>>(w1, w1h, w1l);
    k_wsplit<<<(CC*K1 + 255)/256, 256>>>(w2, w2h, w2l);

    // GEMM1: scores[n][p] = pn . fpat^T  (M=N=4096, K=1152)
    mgemm<<<dim3(32, 32, BT), 256, MGEMM_SMEM>>>(
        pnh, pnl, fph, fpl, bufA, K1, NP,
        (size_t)NP * K1, (size_t)NP * K1, (size_t)NP * NP, nullptr, 0);

    k_fuse<<<16384, 256>>>(bufA, bufB);
    k_perm<<<BT * NP, 256>>>(bufB, bufA);
    k_fuse<<<16384, 256>>>(bufA, bufB);

    k_smax1<<<dim3(16, 32, BT), 256>>>(bufB);
    k_smax2<<<32, 256>>>();
    k_smax3T<<<dim3(128, 128, BT), 256>>>(bufB);

    // GEMM2: yblk[q][p] = sum_m rawT[q][m] * sT[p][m]  (M=2048, N=4096, K=4096)
    mgemm<<<dim3(32, 16, BT), 256, MGEMM_SMEM>>>(
        rth, rtl, sth, stl, yblk, NP, NP,
        (size_t)QQ * NP, (size_t)NP * NP, (size_t)QQ * NP, nullptr, 0);

    k_gather<<<4096, 256>>>();

    // conv1 + ELU: h[c][p] = elu(sum_k w1[c][k] col[p][k] + b1[c])
    k_im2colB<<<16384, 256>>>(yb);
    mgemm<<<dim3(HWF / 128, 1, BT), 256, MGEMM_SMEM>>>(
        w1h, w1l, colh, coll, hb, K1, HWF,
        (size_t)0, (size_t)HWF * K1, (size_t)CC * HWF, b1, 1);

    // conv2 + ELU
    k_im2colB<<<16384, 256>>>(hb);
    mgemm<<<dim3(HWF / 128, 1, BT), 256, MGEMM_SMEM>>>(
        w2h, w2l, colh, coll, out, K1, HWF,
        (size_t)0, (size_t)HWF * K1, (size_t)CC * HWF, b2, 1);
}

// round 5
// speedup vs baseline: 4.6578x; 1.7221x over previous
#include <cuda_runtime.h>
#include <cuda_bf16.h>
#include <cuda_fp16.h>
#include <math.h>
#include <stdint.h>

#define BT 2
#define CC 128
#define HH 128
#define WW 128
#define HS 64
#define NP 4096
#define K1 1152
#define QQ 2048
#define HWF 16384
#define SCALEF 10.0f

// ===================== scratch =====================
__device__ __align__(256) __nv_bfloat16 g_bh [(size_t)BT*NP*CC];  // b half-res [n][c] hi
__device__ __align__(256) __nv_bfloat16 g_bl [(size_t)BT*NP*CC];
__device__ __align__(256) __nv_bfloat16 g_fh [(size_t)BT*NP*CC];  // f half-res [p][c] hi
__device__ __align__(256) __nv_bfloat16 g_fl [(size_t)BT*NP*CC];
__device__ __align__(256) __half        g_rt16[(size_t)BT*QQ*NP]; // raw patches T [q][m] fp16
__device__ __align__(256) __half        g_sT16[(size_t)BT*NP*NP]; // softmax T [p][m] fp16
__device__ __align__(256) __nv_bfloat16 g_col_h[(size_t)BT*HWF*K1];
__device__ __align__(256) __nv_bfloat16 g_col_l[(size_t)BT*HWF*K1];
__device__ __align__(256) __nv_bfloat16 g_w1h[CC*K1], g_w1l[CC*K1], g_w2h[CC*K1], g_w2l[CC*K1];
__device__ float g_bufA[(size_t)BT*NP*NP];
__device__ float g_bufB[(size_t)BT*NP*NP];
__device__ float g_yblk[(size_t)BT*QQ*NP];
__device__ float g_y   [(size_t)BT*CC*HWF];
__device__ float g_h   [(size_t)BT*CC*HWF];
__device__ float g_eq  [NP];
__device__ float g_inv [BT*NP];
__device__ float g_pmax[BT*32*NP];
__device__ float g_psum[BT*32*NP];
__device__ float g_cmax[BT*NP];
__device__ float g_csum[BT*NP];

__device__ __forceinline__ void split_store(__nv_bfloat16* H, __nv_bfloat16* L,
                                            size_t idx, float v) {
    __nv_bfloat16 h = __float2bfloat16(v);
    H[idx] = h;
    L[idx] = __float2bfloat16(v - __bfloat162float(h));
}
__device__ __forceinline__ uint32_t smem_u32(const void* p) {
    uint32_t a;
    asm("{ .reg .u64 t; cvta.to.shared.u64 t, %1; cvt.u32.u64 %0, t; }" : "=r"(a) : "l"(p));
    return a;
}
__device__ __forceinline__ void ldsm_x4(uint32_t (&r)[4], uint32_t addr) {
    asm volatile("ldmatrix.sync.aligned.m8n8.x4.shared.b16 {%0,%1,%2,%3}, [%4];"
                 : "=r"(r[0]), "=r"(r[1]), "=r"(r[2]), "=r"(r[3]) : "r"(addr));
}
__device__ __forceinline__ void mma_bf16(float (&d)[4], const uint32_t (&a)[4],
                                         uint32_t b0, uint32_t b1) {
    asm volatile("mma.sync.aligned.m16n8k16.row.col.f32.bf16.bf16.f32 "
        "{%0,%1,%2,%3}, {%4,%5,%6,%7}, {%8,%9}, {%0,%1,%2,%3};"
        : "+f"(d[0]), "+f"(d[1]), "+f"(d[2]), "+f"(d[3])
        : "r"(a[0]), "r"(a[1]), "r"(a[2]), "r"(a[3]), "r"(b0), "r"(b1));
}
__device__ __forceinline__ void mma_f16(float (&d)[4], const uint32_t (&a)[4],
                                        uint32_t b0, uint32_t b1) {
    asm volatile("mma.sync.aligned.m16n8k16.row.col.f32.f16.f16.f32 "
        "{%0,%1,%2,%3}, {%4,%5,%6,%7}, {%8,%9}, {%0,%1,%2,%3};"
        : "+f"(d[0]), "+f"(d[1]), "+f"(d[2]), "+f"(d[3])
        : "r"(a[0]), "r"(a[1]), "r"(a[2]), "r"(a[3]), "r"(b0), "r"(b1));
}
__device__ __forceinline__ void cpasync16(uint32_t saddr, const void* g) {
    asm volatile("cp.async.cg.shared.global [%0], [%1], 16;" :: "r"(saddr), "l"(g));
}

// ===================== prep =====================
// half-res channel-major bf16 split: dst[b][n][c] = src[b][c][2y][2x]
__global__ void k_half(const float* __restrict__ src, __nv_bfloat16* H, __nv_bfloat16* L) {
    int idx = blockIdx.x * blockDim.x + threadIdx.x;
    if (idx >= BT * NP * CC) return;
    int c = idx & 127;
    int t = idx >> 7;
    int n = t & 4095;
    int b = t >> 12;
    int y = n >> 6, x = n & 63;
    float v = src[(((size_t)b*CC + c)*HH + 2*y)*WW + 2*x];
    split_store(H, L, (size_t)idx, v);
}

// invnorm[b][n] = 1/max(||3x3xC patch of b_half at n||, 1e-4)
__global__ void k_norm(const float* __restrict__ bg) {
    int bn = blockIdx.x;
    int b = bn / NP, n = bn % NP;
    int ny = n / HS, nx = n % HS;
    int c = threadIdx.x;
    float ss = 0.f;
#pragma unroll
    for (int i = 0; i < 3; i++)
#pragma unroll
        for (int jj = 0; jj < 3; jj++) {
            int y = ny + i - 1, x = nx + jj - 1;
            if ((unsigned)y < HS && (unsigned)x < HS) {
                float v = bg[(((size_t)b*CC + c)*HH + 2*y)*WW + 2*x];
                ss += v * v;
            }
        }
    __shared__ float red[128];
    red[c] = ss;
    __syncthreads();
    for (int s = 64; s > 0; s >>= 1) {
        if (c < s) red[c] += red[c + s];
        __syncthreads();
    }
    if (c == 0)
        g_inv[bn] = 1.f / fmaxf(sqrtf(red[0]), 1e-4f);
}

__global__ void k_rawTh(const float* __restrict__ bg) {
    const size_t total = (size_t)BT * QQ * NP;
    const size_t stride = (size_t)gridDim.x * blockDim.x;
    for (size_t idx = (size_t)blockIdx.x * blockDim.x + threadIdx.x; idx < total; idx += stride) {
        int m = (int)(idx % NP);
        size_t t = idx / NP;
        int q = (int)(t % QQ);
        int b = (int)(t / QQ);
        int c = q >> 4, tt = q & 15, di = tt >> 2, dj = tt & 3;
        int my = m / HS, mx = m % HS;
        int Y = 2*my + di - 1, X = 2*mx + dj - 1;
        float v = 0.f;
        if ((unsigned)Y < HH && (unsigned)X < WW)
            v = bg[(((size_t)b*CC + c)*HH + Y)*WW + X];
        g_rt16[idx] = __float2half(v);
    }
}

__global__ void k_eq(const float* __restrict__ mask) {
    int n = blockIdx.x * blockDim.x + threadIdx.x;
    if (n >= NP) return;
    int ny = n / HS, nx = n % HS;
    float s = 0.f;
#pragma unroll
    for (int i = 0; i < 3; i++)
#pragma unroll
        for (int j = 0; j < 3; j++) {
            int y = ny + i - 1, x = nx + j - 1;
            if ((unsigned)y < HS && (unsigned)x < HS)
                s += mask[(2*y)*WW + 2*x];
        }
    g_eq[n] = ((s / 9.f) == 0.f) ? 1.f : 0.f;
}

__global__ void k_wsplit(const float* __restrict__ w, __nv_bfloat16* H, __nv_bfloat16* L) {
    int idx = blockIdx.x * blockDim.x + threadIdx.x;
    if (idx >= CC * K1) return;
    split_store(H, L, (size_t)idx, w[idx]);
}

// ===================== bf16-split GEMM (3-term) =====================
#define KT 32
#define STAGES 3
#define STAGE_BYTES (4*128*KT*2)           // 32768
#define MGEMM_SMEM (STAGES*STAGE_BYTES)

__global__ void __launch_bounds__(256, 1) mgemm(
    const __nv_bfloat16* __restrict__ Ah, const __nv_bfloat16* __restrict__ Al,
    const __nv_bfloat16* __restrict__ Bh, const __nv_bfloat16* __restrict__ Bl,
    float* __restrict__ C, int K, int N,
    size_t sA, size_t sB, size_t sC,
    const float* __restrict__ bias, int act)
{
    extern __shared__ char sm[];
    const uint32_t smb = smem_u32(sm);
    const int tid = threadIdx.x;
    const int bz = blockIdx.z;
    const int bm = blockIdx.y * 128;
    const int bn = blockIdx.x * 128;
    C += sC * bz;

    const int j   = tid >> 6;
    const int l64 = tid & 63;
    const int rbase = (j < 2) ? bm : bn;
    const __nv_bfloat16* src =
        (j == 0) ? Ah + sA*bz : (j == 1) ? Al + sA*bz : (j == 2) ? Bh + sB*bz : Bl + sB*bz;

    const int NC = K >> 5;

#pragma unroll
    for (int s = 0; s < STAGES - 1; s++) {
        const int kc = s * KT;
#pragma unroll
        for (int i = 0; i < 8; i++) {
            int id = l64 + i * 64;
            int row = id >> 2, ch = id & 3;
            const void* g = src + (size_t)(rbase + row) * K + kc + ch * 8;
            uint32_t sa = smb + s*STAGE_BYTES + j*8192 + row*64 + ((ch ^ ((row >> 1) & 3)) << 4);
            cpasync16(sa, g);
        }
        asm volatile("cp.async.commit_group;");
    }

    const int wid = tid >> 5, lane = tid & 31;
    const int wm = wid & 1, wn = wid >> 1;

    float acc[4][4][4];
#pragma unroll
    for (int a = 0; a < 4; a++)
#pragma unroll
        for (int bb = 0; bb < 4; bb++)
#pragma unroll
            for (int c = 0; c < 4; c++) acc[a][bb][c] = 0.f;

    for (int i = 0; i < NC; i++) {
        asm volatile("cp.async.wait_group 1;");
        __syncthreads();

        if (i + STAGES - 1 < NC) {
            const int s2 = (i + STAGES - 1) % STAGES;
            const int kc = (i + STAGES - 1) * KT;
#pragma unroll
            for (int it = 0; it < 8; it++) {
                int id = l64 + it * 64;
                int row = id >> 2, ch = id & 3;
                const void* g = src + (size_t)(rbase + row) * K + kc + ch * 8;
                uint32_t sa = smb + s2*STAGE_BYTES + j*8192 + row*64 + ((ch ^ ((row >> 1) & 3)) << 4);
                cpasync16(sa, g);
            }
        }
        asm volatile("cp.async.commit_group;");

        const uint32_t stb = smb + (i % STAGES) * STAGE_BYTES;
#pragma unroll
        for (int h = 0; h < 2; h++) {
            uint32_t ah[4][4], al[4][4];
            uint32_t bh[4][2], bl[4][2];
#pragma unroll
            for (int tm = 0; tm < 4; tm++) {
                int row = wm*64 + tm*16 + (lane & 15);
                int ch  = 2*h + (lane >> 4);
                uint32_t ad = stb + row*64 + ((ch ^ ((row >> 1) & 3)) << 4);
                ldsm_x4(ah[tm], ad);
                ldsm_x4(al[tm], ad + 8192);
            }
#pragma unroll
            for (int tp = 0; tp < 2; tp++) {
                int row = wn*32 + tp*16 + ((lane >> 4) << 3) + (lane & 7);
                int ch  = 2*h + ((lane >> 3) & 1);
                uint32_t bd = stb + 16384 + row*64 + ((ch ^ ((row >> 1) & 3)) << 4);
                uint32_t r[4];
                ldsm_x4(r, bd);
                bh[tp*2][0] = r[0]; bh[tp*2][1] = r[1];
                bh[tp*2+1][0] = r[2]; bh[tp*2+1][1] = r[3];
                ldsm_x4(r, bd + 8192);
                bl[tp*2][0] = r[0]; bl[tp*2][1] = r[1];
                bl[tp*2+1][0] = r[2]; bl[tp*2+1][1] = r[3];
            }
#pragma unroll
            for (int tm = 0; tm < 4; tm++)
#pragma unroll
                for (int tn = 0; tn < 4; tn++) {
                    mma_bf16(acc[tm][tn], ah[tm], bh[tn][0], bh[tn][1]);
                    mma_bf16(acc[tm][tn], ah[tm], bl[tn][0], bl[tn][1]);
                    mma_bf16(acc[tm][tn], al[tm], bh[tn][0], bh[tn][1]);
                }
        }
    }

#pragma unroll
    for (int tm = 0; tm < 4; tm++) {
        int row = bm + wm*64 + tm*16 + (lane >> 2);
#pragma unroll
        for (int hf = 0; hf < 2; hf++) {
            int r = row + hf*8;
            float bv = bias ? bias[r] : 0.f;
            float* dst = C + (size_t)r * N + bn + wn*32 + (lane & 3)*2;
#pragma unroll
            for (int tn = 0; tn < 4; tn++) {
                float x0 = acc[tm][tn][hf*2+0] + bv;
                float x1 = acc[tm][tn][hf*2+1] + bv;
                if (act) {
                    x0 = x0 > 0.f ? x0 : expf(x0) - 1.f;
                    x1 = x1 > 0.f ? x1 : expf(x1) - 1.f;
                }
                *(float2*)(dst + tn*8) = make_float2(x0, x1);
            }
        }
    }
}

// ===================== fp16 single GEMM =====================
#define HSTAGE_BYTES (2*128*KT*2)          // 16384
#define HGEMM_SMEM (STAGES*HSTAGE_BYTES)   // 49152

__global__ void __launch_bounds__(256, 1) hgemm(
    const __half* __restrict__ A, const __half* __restrict__ B,
    float* __restrict__ C, int K, int N,
    size_t sA, size_t sB, size_t sC)
{
    extern __shared__ char sm[];
    const uint32_t smb = smem_u32(sm);
    const int tid = threadIdx.x;
    const int bz = blockIdx.z;
    const int bm = blockIdx.y * 128;
    const int bn = blockIdx.x * 128;
    C += sC * bz;

    const int j    = tid >> 7;        // 0:A 1:B
    const int l128 = tid & 127;
    const int rbase = j ? bn : bm;
    const __half* src = j ? B + sB*bz : A + sA*bz;

    const int NC = K >> 5;

#pragma unroll
    for (int s = 0; s < STAGES - 1; s++) {
        const int kc = s * KT;
#pragma unroll
        for (int i = 0; i < 4; i++) {
            int id = l128 + i * 128;
            int row = id >> 2, ch = id & 3;
            const void* g = src + (size_t)(rbase + row) * K + kc + ch * 8;
            uint32_t sa = smb + s*HSTAGE_BYTES + j*8192 + row*64 + ((ch ^ ((row >> 1) & 3)) << 4);
            cpasync16(sa, g);
        }
        asm volatile("cp.async.commit_group;");
    }

    const int wid = tid >> 5, lane = tid & 31;
    const int wm = wid & 1, wn = wid >> 1;

    float acc[4][4][4];
#pragma unroll
    for (int a = 0; a < 4; a++)
#pragma unroll
        for (int bb = 0; bb < 4; bb++)
#pragma unroll
            for (int c = 0; c < 4; c++) acc[a][bb][c] = 0.f;

    for (int i = 0; i < NC; i++) {
        asm volatile("cp.async.wait_group 1;");
        __syncthreads();

        if (i + STAGES - 1 < NC) {
            const int s2 = (i + STAGES - 1) % STAGES;
            const int kc = (i + STAGES - 1) * KT;
#pragma unroll
            for (int it = 0; it < 4; it++) {
                int id = l128 + it * 128;
                int row = id >> 2, ch = id & 3;
                const void* g = src + (size_t)(rbase + row) * K + kc + ch * 8;
                uint32_t sa = smb + s2*HSTAGE_BYTES + j*8192 + row*64 + ((ch ^ ((row >> 1) & 3)) << 4);
                cpasync16(sa, g);
            }
        }
        asm volatile("cp.async.commit_group;");

        const uint32_t stb = smb + (i % STAGES) * HSTAGE_BYTES;
#pragma unroll
        for (int h = 0; h < 2; h++) {
            uint32_t ah[4][4];
            uint32_t bh[4][2];
#pragma unroll
            for (int tm = 0; tm < 4; tm++) {
                int row = wm*64 + tm*16 + (lane & 15);
                int ch  = 2*h + (lane >> 4);
                uint32_t ad = stb + row*64 + ((ch ^ ((row >> 1) & 3)) << 4);
                ldsm_x4(ah[tm], ad);
            }
#pragma unroll
            for (int tp = 0; tp < 2; tp++) {
                int row = wn*32 + tp*16 + ((lane >> 4) << 3) + (lane & 7);
                int ch  = 2*h + ((lane >> 3) & 1);
                uint32_t bd = stb + 8192 + row*64 + ((ch ^ ((row >> 1) & 3)) << 4);
                uint32_t r[4];
                ldsm_x4(r, bd);
                bh[tp*2][0] = r[0]; bh[tp*2][1] = r[1];
                bh[tp*2+1][0] = r[2]; bh[tp*2+1][1] = r[3];
            }
#pragma unroll
            for (int tm = 0; tm < 4; tm++)
#pragma unroll
                for (int tn = 0; tn < 4; tn++)
                    mma_f16(acc[tm][tn], ah[tm], bh[tn][0], bh[tn][1]);
        }
    }

#pragma unroll
    for (int tm = 0; tm < 4; tm++) {
        int row = bm + wm*64 + tm*16 + (lane >> 2);
#pragma unroll
        for (int hf = 0; hf < 2; hf++) {
            int r = row + hf*8;
            float* dst = C + (size_t)r * N + bn + wn*32 + (lane & 3)*2;
#pragma unroll
            for (int tn = 0; tn < 4; tn++)
                *(float2*)(dst + tn*8) = make_float2(acc[tm][tn][hf*2+0], acc[tm][tn][hf*2+1]);
        }
    }
}

// ===================== stencil: s0[n][p] = inv[n] * sum_d G[n+d][p+d] =====================
__global__ void __launch_bounds__(256) k_stencil9(const float* __restrict__ G,
                                                  float* __restrict__ out) {
    __shared__ float t3[3][64][64];
    int bid = blockIdx.x;
    int b = bid >> 12;
    int rest = bid & 4095;
    int ny = rest >> 6, py = rest & 63;
    const float* Gb = G + (size_t)b * NP * NP;
    float* ob = out + (size_t)b * NP * NP;
    int tid = threadIdx.x;

#pragma unroll
    for (int dy = 0; dy < 3; dy++) {
        int gy = ny + dy - 1, gpy = py + dy - 1;
        bool ok = (unsigned)gy < 64 && (unsigned)gpy < 64;
        for (int idx = tid; idx < 4096; idx += 256) {
            int i = idx >> 6, jj = idx & 63;
            t3[dy][i][jj] = ok ? Gb[((size_t)(gy*64 + i)) * NP + gpy*64 + jj] : 0.f;
        }
    }
    __syncthreads();

    int px = tid & 63;
    int nx0 = tid >> 6;
    for (int nx = nx0; nx < 64; nx += 4) {
        float s = 0.f;
#pragma unroll
        for (int dy = 0; dy < 3; dy++)
#pragma unroll
            for (int dx = -1; dx <= 1; dx++) {
                int a = nx + dx, c = px + dx;
                if ((unsigned)a < 64 && (unsigned)c < 64)
                    s += t3[dy][a][c];
            }
        ob[((size_t)(ny*64 + nx)) * NP + py*64 + px] = s * g_inv[b*NP + ny*64 + nx];
    }
}

// ===================== fuse1 + permutation =====================
// out[(nx,ny)][(px,py)] = fused1[(ny,nx)][(py,px)], fused1 = flat diag 3-tap
__global__ void k_fuseperm(const float* __restrict__ in, float* __restrict__ out) {
    __shared__ float tile[64 * 65];
    int brow = blockIdx.x;
    int b = brow / NP, rp = brow % NP;
    int nx = rp >> 6, ny = rp & 63;
    int r = ny * 64 + nx;
    const float* src = in + (size_t)b * NP * NP;
    float*       dst = out + ((size_t)b * NP + rp) * NP;
    int tid = threadIdx.x;
    for (int k = tid; k < NP; k += 256) {
        float f = src[(size_t)r * NP + k];
        if (r > 0 && k > 0)           f += src[(size_t)(r-1) * NP + k - 1];
        if (r < NP-1 && k < NP-1)     f += src[(size_t)(r+1) * NP + k + 1];
        tile[(k & 63) * 65 + (k >> 6)] = f;
    }
    __syncthreads();
    for (int j = tid; j < NP; j += 256)
        dst[j] = tile[(j >> 6) * 65 + (j & 63)];
}

// ===================== softmax (fuse2 on the fly) =====================
__global__ void k_smax1(const float* __restrict__ in) {
    int col = blockIdx.x * 256 + threadIdx.x;
    int chunk = blockIdx.y;
    int b = blockIdx.z;
    const float* base = in + (size_t)b * NP * NP;
    float mx = -1e30f, sm = 0.f;
    int r0 = chunk * 128;
    for (int r = r0; r < r0 + 128; r++) {
        float v = base[(size_t)r * NP + col];
        if (r > 0 && col > 0)         v += base[(size_t)(r-1) * NP + col - 1];
        if (r < NP-1 && col < NP-1)   v += base[(size_t)(r+1) * NP + col + 1];
        float l = v * (g_eq[r] * SCALEF);
        if (l > mx) { sm = sm * expf(mx - l) + 1.f; mx = l; }
        else        { sm += expf(l - mx); }
    }
    g_pmax[((size_t)b * 32 + chunk) * NP + col] = mx;
    g_psum[((size_t)b * 32 + chunk) * NP + col] = sm;
}

__global__ void k_smax2() {
    int idx = blockIdx.x * blockDim.x + threadIdx.x;
    if (idx >= BT * NP) return;
    int b = idx / NP, col = idx % NP;
    float M = -1e30f;
    for (int i = 0; i < 32; i++)
        M = fmaxf(M, g_pmax[((size_t)b * 32 + i) * NP + col]);
    float S = 0.f;
    for (int i = 0; i < 32; i++)
        S += g_psum[((size_t)b * 32 + i) * NP + col] *
             expf(g_pmax[((size_t)b * 32 + i) * NP + col] - M);
    g_cmax[idx] = M;
    g_csum[idx] = S;
}

// fuse2 + softmax + transpose -> fp16 sT[p][m]
__global__ void k_smax3T(const float* __restrict__ in) {
    __shared__ float raw[34][35];
    int b = blockIdx.z;
    int r0 = blockIdx.y * 32;   // m
    int c0 = blockIdx.x * 32;   // p
    int tid = threadIdx.x;
    const float* base = in + (size_t)b * NP * NP;
    for (int idx = tid; idx < 34*34; idx += 256) {
        int i = idx / 34, jj = idx % 34;
        int rr = r0 - 1 + i, cc = c0 - 1 + jj;
        raw[i][jj] = ((unsigned)rr < NP && (unsigned)cc < NP)
                   ? base[(size_t)rr * NP + cc] : 0.f;
    }
    __syncthreads();
    int tx = tid & 31, ty = tid >> 5;
#pragma unroll
    for (int k = 0; k < 4; k++) {
        int pl = ty + k * 8;
        int p = c0 + pl;
        int m = r0 + tx;
        float fused = raw[tx+1][pl+1] + raw[tx][pl] + raw[tx+2][pl+2];
        float eq = g_eq[m];
        float l = fused * (eq * SCALEF);
        float v = expf(l - g_cmax[b * NP + p]) / g_csum[b * NP + p] * eq;
        g_sT16[((size_t)b * NP + p) * NP + m] = __float2half(v);
    }
}

// ===================== transposed-conv gather + im2col =====================
__global__ void k_gather() {
    const int total = BT * CC * HWF;
    for (int idx = blockIdx.x * blockDim.x + threadIdx.x; idx < total;
         idx += gridDim.x * blockDim.x) {
        int X = idx & 127;
        int t = idx >> 7;
        int Y = t & 127; t >>= 7;
        int c = t & 127;
        int b = t >> 7;
        float acc = 0.f;
#pragma unroll
        for (int ki = 0; ki < 4; ki++) {
            int tyy = Y + 1 - ki;
            if (tyy < 0 || (tyy & 1)) continue;
            int yq = tyy >> 1;
            if (yq >= HS) continue;
#pragma unroll
            for (int kj = 0; kj < 4; kj++) {
                int txx = X + 1 - kj;
                if (txx < 0 || (txx & 1)) continue;
                int xq = txx >> 1;
                if (xq >= HS) continue;
                acc += g_yblk[((size_t)b * QQ + c * 16 + ki * 4 + kj) * NP + yq * HS + xq];
            }
        }
        g_y[idx] = acc * 0.25f;
    }
}

__global__ void k_im2colB(const float* __restrict__ src) {
    const size_t total = (size_t)BT * HWF * K1;
    const size_t stride = (size_t)gridDim.x * blockDim.x;
    for (size_t idx = (size_t)blockIdx.x * blockDim.x + threadIdx.x; idx < total; idx += stride) {
        int k = (int)(idx % K1);
        size_t t = idx / K1;
        int p = (int)(t % HWF);
        int b = (int)(t / HWF);
        int c = k / 9, kk = k % 9, ki = kk / 3, kj = kk % 3;
        int Y = p >> 7, X = p & 127;
        int y = Y + ki - 1, x = X + kj - 1;
        float v = 0.f;
        if ((unsigned)y < HH && (unsigned)x < WW)
            v = src[(((size_t)b * CC + c) * HH + y) * WW + x];
        split_store(g_col_h, g_col_l, idx, v);
    }
}

// ===================== host orchestration =====================
extern "C" void kernel_launch(void* const* d_in, const int* in_sizes, int n_in,
                              void* d_out, int out_size) {
    const float* fg   = (const float*)d_in[0];
    const float* bg   = (const float*)d_in[1];
    const float* mask = (const float*)d_in[2];
    const float* w1   = (const float*)d_in[3];
    const float* b1   = (const float*)d_in[4];
    const float* w2   = (const float*)d_in[5];
    const float* b2   = (const float*)d_in[6];
    float* out = (float*)d_out;

    cudaFuncSetAttribute(mgemm, cudaFuncAttributeMaxDynamicSharedMemorySize, MGEMM_SMEM);
    cudaFuncSetAttribute(hgemm, cudaFuncAttributeMaxDynamicSharedMemorySize, HGEMM_SMEM);

    __nv_bfloat16 *bh, *bl, *fh, *fl, *colh, *coll, *w1h, *w1l, *w2h, *w2l;
    __half *rt16, *st16;
    float *bufA, *bufB, *yblk, *yb, *hb;
    cudaGetSymbolAddress((void**)&bh, g_bh);     cudaGetSymbolAddress((void**)&bl, g_bl);
    cudaGetSymbolAddress((void**)&fh, g_fh);     cudaGetSymbolAddress((void**)&fl, g_fl);
    cudaGetSymbolAddress((void**)&rt16, g_rt16); cudaGetSymbolAddress((void**)&st16, g_sT16);
    cudaGetSymbolAddress((void**)&colh, g_col_h); cudaGetSymbolAddress((void**)&coll, g_col_l);
    cudaGetSymbolAddress((void**)&w1h, g_w1h);   cudaGetSymbolAddress((void**)&w1l, g_w1l);
    cudaGetSymbolAddress((void**)&w2h, g_w2h);   cudaGetSymbolAddress((void**)&w2l, g_w2l);
    cudaGetSymbolAddress((void**)&bufA, g_bufA);
    cudaGetSymbolAddress((void**)&bufB, g_bufB);
    cudaGetSymbolAddress((void**)&yblk, g_yblk);
    cudaGetSymbolAddress((void**)&yb,   g_y);
    cudaGetSymbolAddress((void**)&hb,   g_h);

    // prep
    k_half  <<<(BT*NP*CC + 255)/256, 256>>>(bg, bh, bl);
    k_half  <<<(BT*NP*CC + 255)/256, 256>>>(fg, fh, fl);
    k_norm  <<<BT * NP, 128>>>(bg);
    k_rawTh <<<8192, 256>>>(bg);
    k_eq    <<<16, 256>>>(mask);
    k_wsplit<<<(CC*K1 + 255)/256, 256>>>(w1, w1h, w1l);
    k_wsplit<<<(CC*K1 + 255)/256, 256>>>(w2, w2h, w2l);

    // G[u][v] = sum_c b[u][c] f[v][c]   (M=N=4096, K=128)  -> bufA
    mgemm<<<dim3(32, 32, BT), 256, MGEMM_SMEM>>>(
        bh, bl, fh, fl, bufA, CC, NP,
        (size_t)NP * CC, (size_t)NP * CC, (size_t)NP * NP, nullptr, 0);

    // scores = 9-tap diagonal stencil / norm  -> bufB
    k_stencil9<<<BT * 4096, 256>>>(bufA, bufB);

    // fuse1 + permutation -> bufA
    k_fuseperm<<<BT * NP, 256>>>(bufB, bufA);

    // fuse2 on-the-fly + softmax
    k_smax1<<<dim3(16, 32, BT), 256>>>(bufA);
    k_smax2<<<32, 256>>>();
    k_smax3T<<<dim3(128, 128, BT), 256>>>(bufA);

    // GEMM2: yblk[q][p] = sum_m rt[q][m] * sT[p][m]  (fp16 single)
    hgemm<<<dim3(32, 16, BT), 256, HGEMM_SMEM>>>(
        rt16, st16, yblk, NP, NP,
        (size_t)QQ * NP, (size_t)NP * NP, (size_t)QQ * NP);

    k_gather<<<4096, 256>>>();

    // conv1 + ELU
    k_im2colB<<<16384, 256>>>(yb);
    mgemm<<<dim3(HWF / 128, 1, BT), 256, MGEMM_SMEM>>>(
        w1h, w1l, colh, coll, hb, K1, HWF,
        (size_t)0, (size_t)HWF * K1, (size_t)CC * HWF, b1, 1);

    // conv2 + ELU
    k_im2colB<<<16384, 256>>>(hb);
    mgemm<<<dim3(HWF / 128, 1, BT), 256, MGEMM_SMEM>>>(
        w2h, w2l, colh, coll, out, K1, HWF,
        (size_t)0, (size_t)HWF * K1, (size_t)CC * HWF, b2, 1);
}

// round 6
// speedup vs baseline: 5.1223x; 1.0997x over previous
#include <cuda_runtime.h>
#include <cuda_bf16.h>
#include <cuda_fp16.h>
#include <math.h>
#include <stdint.h>

#define BT 2
#define CC 128
#define HH 128
#define WW 128
#define HS 64
#define NP 4096
#define K1 1152
#define QQ 2048
#define HWF 16384
#define SCALEF 10.0f

// ===================== scratch =====================
__device__ __align__(256) __nv_bfloat16 g_bh [(size_t)BT*NP*CC];
__device__ __align__(256) __nv_bfloat16 g_bl [(size_t)BT*NP*CC];
__device__ __align__(256) __nv_bfloat16 g_fh [(size_t)BT*NP*CC];
__device__ __align__(256) __nv_bfloat16 g_fl [(size_t)BT*NP*CC];
__device__ __align__(256) __half        g_rt16[(size_t)BT*QQ*NP];  // raw patches T [q][m]
__device__ __align__(256) __half        g_sT16[(size_t)BT*NP*NP];  // softmax T [p][m]
__device__ __align__(256) __half        g_col16[(size_t)BT*HWF*K1];
__device__ __align__(256) __half        g_w1h16[CC*K1], g_w1l16[CC*K1];
__device__ __align__(256) __half        g_w2h16[CC*K1], g_w2l16[CC*K1];
__device__ float g_bufA[(size_t)BT*NP*NP];
__device__ float g_bufB[(size_t)BT*NP*NP];
__device__ float g_yblk[(size_t)BT*QQ*NP];
__device__ float g_y   [(size_t)BT*CC*HWF];
__device__ float g_h   [(size_t)BT*CC*HWF];
__device__ float g_eq  [NP];
__device__ float g_inv [BT*NP];
__device__ float g_pmax[BT*32*NP];
__device__ float g_psum[BT*32*NP];
__device__ float g_cmax[BT*NP];
__device__ float g_csum[BT*NP];

__device__ __forceinline__ void split_store(__nv_bfloat16* H, __nv_bfloat16* L,
                                            size_t idx, float v) {
    __nv_bfloat16 h = __float2bfloat16(v);
    H[idx] = h;
    L[idx] = __float2bfloat16(v - __bfloat162float(h));
}
__device__ __forceinline__ void split_store16(__half* H, __half* L, size_t idx, float v) {
    __half h = __float2half(v);
    H[idx] = h;
    L[idx] = __float2half(v - __half2float(h));
}
__device__ __forceinline__ uint32_t smem_u32(const void* p) {
    uint32_t a;
    asm("{ .reg .u64 t; cvta.to.shared.u64 t, %1; cvt.u32.u64 %0, t; }" : "=r"(a) : "l"(p));
    return a;
}
__device__ __forceinline__ void ldsm_x4(uint32_t (&r)[4], uint32_t addr) {
    asm volatile("ldmatrix.sync.aligned.m8n8.x4.shared.b16 {%0,%1,%2,%3}, [%4];"
                 : "=r"(r[0]), "=r"(r[1]), "=r"(r[2]), "=r"(r[3]) : "r"(addr));
}
__device__ __forceinline__ void mma_bf16(float (&d)[4], const uint32_t (&a)[4],
                                         uint32_t b0, uint32_t b1) {
    asm volatile("mma.sync.aligned.m16n8k16.row.col.f32.bf16.bf16.f32 "
        "{%0,%1,%2,%3}, {%4,%5,%6,%7}, {%8,%9}, {%0,%1,%2,%3};"
        : "+f"(d[0]), "+f"(d[1]), "+f"(d[2]), "+f"(d[3])
        : "r"(a[0]), "r"(a[1]), "r"(a[2]), "r"(a[3]), "r"(b0), "r"(b1));
}
__device__ __forceinline__ void mma_f16(float (&d)[4], const uint32_t (&a)[4],
                                        uint32_t b0, uint32_t b1) {
    asm volatile("mma.sync.aligned.m16n8k16.row.col.f32.f16.f16.f32 "
        "{%0,%1,%2,%3}, {%4,%5,%6,%7}, {%8,%9}, {%0,%1,%2,%3};"
        : "+f"(d[0]), "+f"(d[1]), "+f"(d[2]), "+f"(d[3])
        : "r"(a[0]), "r"(a[1]), "r"(a[2]), "r"(a[3]), "r"(b0), "r"(b1));
}
__device__ __forceinline__ void cpasync16(uint32_t saddr, const void* g) {
    asm volatile("cp.async.cg.shared.global [%0], [%1], 16;" :: "r"(saddr), "l"(g));
}

// ===================== prep =====================
__global__ void k_half(const float* __restrict__ src, __nv_bfloat16* H, __nv_bfloat16* L) {
    int idx = blockIdx.x * blockDim.x + threadIdx.x;
    if (idx >= BT * NP * CC) return;
    int c = idx & 127;
    int t = idx >> 7;
    int n = t & 4095;
    int b = t >> 12;
    int y = n >> 6, x = n & 63;
    float v = src[(((size_t)b*CC + c)*HH + 2*y)*WW + 2*x];
    split_store(H, L, (size_t)idx, v);
}

__global__ void k_norm(const float* __restrict__ bg) {
    int bn = blockIdx.x;
    int b = bn / NP, n = bn % NP;
    int ny = n / HS, nx = n % HS;
    int c = threadIdx.x;
    float ss = 0.f;
#pragma unroll
    for (int i = 0; i < 3; i++)
#pragma unroll
        for (int jj = 0; jj < 3; jj++) {
            int y = ny + i - 1, x = nx + jj - 1;
            if ((unsigned)y < HS && (unsigned)x < HS) {
                float v = bg[(((size_t)b*CC + c)*HH + 2*y)*WW + 2*x];
                ss += v * v;
            }
        }
    __shared__ float red[128];
    red[c] = ss;
    __syncthreads();
    for (int s = 64; s > 0; s >>= 1) {
        if (c < s) red[c] += red[c + s];
        __syncthreads();
    }
    if (c == 0)
        g_inv[bn] = 1.f / fmaxf(sqrtf(red[0]), 1e-4f);
}

__global__ void k_rawTh(const float* __restrict__ bg) {
    const size_t total = (size_t)BT * QQ * NP;
    const size_t stride = (size_t)gridDim.x * blockDim.x;
    for (size_t idx = (size_t)blockIdx.x * blockDim.x + threadIdx.x; idx < total; idx += stride) {
        int m = (int)(idx & (NP - 1));
        size_t t = idx >> 12;
        int q = (int)(t & (QQ - 1));
        int b = (int)(t >> 11);
        int c = q >> 4, tt = q & 15, di = tt >> 2, dj = tt & 3;
        int my = m >> 6, mx = m & 63;
        int Y = 2*my + di - 1, X = 2*mx + dj - 1;
        float v = 0.f;
        if ((unsigned)Y < HH && (unsigned)X < WW)
            v = bg[(((size_t)b*CC + c)*HH + Y)*WW + X];
        g_rt16[idx] = __float2half(v);
    }
}

__global__ void k_eq(const float* __restrict__ mask) {
    int n = blockIdx.x * blockDim.x + threadIdx.x;
    if (n >= NP) return;
    int ny = n / HS, nx = n % HS;
    float s = 0.f;
#pragma unroll
    for (int i = 0; i < 3; i++)
#pragma unroll
        for (int j = 0; j < 3; j++) {
            int y = ny + i - 1, x = nx + j - 1;
            if ((unsigned)y < HS && (unsigned)x < HS)
                s += mask[(2*y)*WW + 2*x];
        }
    g_eq[n] = ((s / 9.f) == 0.f) ? 1.f : 0.f;
}

__global__ void k_wsplit16(const float* __restrict__ w, __half* H, __half* L) {
    int idx = blockIdx.x * blockDim.x + threadIdx.x;
    if (idx >= CC * K1) return;
    split_store16(H, L, (size_t)idx, w[idx]);
}

// ===================== bf16-split GEMM (3-term, 128x128) — GEMM1 only ========
#define KT 32
#define STAGES 3
#define STAGE_BYTES (4*128*KT*2)
#define MGEMM_SMEM (STAGES*STAGE_BYTES)

__global__ void __launch_bounds__(256, 1) mgemm(
    const __nv_bfloat16* __restrict__ Ah, const __nv_bfloat16* __restrict__ Al,
    const __nv_bfloat16* __restrict__ Bh, const __nv_bfloat16* __restrict__ Bl,
    float* __restrict__ C, int K, int N,
    size_t sA, size_t sB, size_t sC)
{
    extern __shared__ char sm[];
    const uint32_t smb = smem_u32(sm);
    const int tid = threadIdx.x;
    const int bz = blockIdx.z;
    const int bm = blockIdx.y * 128;
    const int bn = blockIdx.x * 128;
    C += sC * bz;

    const int j   = tid >> 6;
    const int l64 = tid & 63;
    const int rbase = (j < 2) ? bm : bn;
    const __nv_bfloat16* src =
        (j == 0) ? Ah + sA*bz : (j == 1) ? Al + sA*bz : (j == 2) ? Bh + sB*bz : Bl + sB*bz;

    const int NC = K >> 5;

#pragma unroll
    for (int s = 0; s < STAGES - 1; s++) {
        const int kc = s * KT;
#pragma unroll
        for (int i = 0; i < 8; i++) {
            int id = l64 + i * 64;
            int row = id >> 2, ch = id & 3;
            const void* g = src + (size_t)(rbase + row) * K + kc + ch * 8;
            uint32_t sa = smb + s*STAGE_BYTES + j*8192 + row*64 + ((ch ^ ((row >> 1) & 3)) << 4);
            cpasync16(sa, g);
        }
        asm volatile("cp.async.commit_group;");
    }

    const int wid = tid >> 5, lane = tid & 31;
    const int wm = wid & 1, wn = wid >> 1;

    float acc[4][4][4];
#pragma unroll
    for (int a = 0; a < 4; a++)
#pragma unroll
        for (int bb = 0; bb < 4; bb++)
#pragma unroll
            for (int c = 0; c < 4; c++) acc[a][bb][c] = 0.f;

    for (int i = 0; i < NC; i++) {
        asm volatile("cp.async.wait_group 1;");
        __syncthreads();

        if (i + STAGES - 1 < NC) {
            const int s2 = (i + STAGES - 1) % STAGES;
            const int kc = (i + STAGES - 1) * KT;
#pragma unroll
            for (int it = 0; it < 8; it++) {
                int id = l64 + it * 64;
                int row = id >> 2, ch = id & 3;
                const void* g = src + (size_t)(rbase + row) * K + kc + ch * 8;
                uint32_t sa = smb + s2*STAGE_BYTES + j*8192 + row*64 + ((ch ^ ((row >> 1) & 3)) << 4);
                cpasync16(sa, g);
            }
        }
        asm volatile("cp.async.commit_group;");

        const uint32_t stb = smb + (i % STAGES) * STAGE_BYTES;
#pragma unroll
        for (int h = 0; h < 2; h++) {
            uint32_t ah[4][4], al[4][4];
            uint32_t bh[4][2], bl[4][2];
#pragma unroll
            for (int tm = 0; tm < 4; tm++) {
                int row = wm*64 + tm*16 + (lane & 15);
                int ch  = 2*h + (lane >> 4);
                uint32_t ad = stb + row*64 + ((ch ^ ((row >> 1) & 3)) << 4);
                ldsm_x4(ah[tm], ad);
                ldsm_x4(al[tm], ad + 8192);
            }
#pragma unroll
            for (int tp = 0; tp < 2; tp++) {
                int row = wn*32 + tp*16 + ((lane >> 4) << 3) + (lane & 7);
                int ch  = 2*h + ((lane >> 3) & 1);
                uint32_t bd = stb + 16384 + row*64 + ((ch ^ ((row >> 1) & 3)) << 4);
                uint32_t r[4];
                ldsm_x4(r, bd);
                bh[tp*2][0] = r[0]; bh[tp*2][1] = r[1];
                bh[tp*2+1][0] = r[2]; bh[tp*2+1][1] = r[3];
                ldsm_x4(r, bd + 8192);
                bl[tp*2][0] = r[0]; bl[tp*2][1] = r[1];
                bl[tp*2+1][0] = r[2]; bl[tp*2+1][1] = r[3];
            }
#pragma unroll
            for (int tm = 0; tm < 4; tm++)
#pragma unroll
                for (int tn = 0; tn < 4; tn++) {
                    mma_bf16(acc[tm][tn], ah[tm], bh[tn][0], bh[tn][1]);
                    mma_bf16(acc[tm][tn], ah[tm], bl[tn][0], bl[tn][1]);
                    mma_bf16(acc[tm][tn], al[tm], bh[tn][0], bh[tn][1]);
                }
        }
    }

#pragma unroll
    for (int tm = 0; tm < 4; tm++) {
        int row = bm + wm*64 + tm*16 + (lane >> 2);
#pragma unroll
        for (int hf = 0; hf < 2; hf++) {
            int r = row + hf*8;
            float* dst = C + (size_t)r * N + bn + wn*32 + (lane & 3)*2;
#pragma unroll
            for (int tn = 0; tn < 4; tn++)
                *(float2*)(dst + tn*8) = make_float2(acc[tm][tn][hf*2+0], acc[tm][tn][hf*2+1]);
        }
    }
}

// ===================== fp16 wide GEMM: 128m x 256n, A 1- or 2-term ===========
// C[r][col] = sum_k A[r][k]*B[col][k] (+ Alo term if AT==2), opt bias+ELU.
template<int AT>
__global__ void __launch_bounds__(256, 1) wgemm(
    const __half* __restrict__ A0, const __half* __restrict__ A1,
    const __half* __restrict__ B,
    float* __restrict__ C, int K, int N,
    size_t sA, size_t sB, size_t sC,
    const float* __restrict__ bias, int act)
{
    constexpr int STAGE = AT*8192 + 16384;
    extern __shared__ char sm[];
    const uint32_t smb = smem_u32(sm);
    const int tid = threadIdx.x;
    const int bz = blockIdx.z;
    const int bm = blockIdx.y * 128;
    const int bn = blockIdx.x * 256;
    C += sC * bz;
    const __half* a0 = A0 + sA * bz;
    const __half* a1 = (AT == 2) ? A1 + sA * bz : nullptr;
    const __half* bp = B + sB * bz;

    const int NC = K >> 5;

    // stage loader (all 256 threads)
    auto load_stage = [&](int s, int kc) {
#pragma unroll
        for (int it = 0; it < 2; it++) {
            int id = tid + it * 256;
            int row = id >> 2, ch = id & 3;
            uint32_t swz = (uint32_t)(row * 64 + ((ch ^ ((row >> 1) & 3)) << 4));
            cpasync16(smb + s*STAGE + swz, a0 + (size_t)(bm + row) * K + kc + ch * 8);
            if (AT == 2)
                cpasync16(smb + s*STAGE + 8192 + swz, a1 + (size_t)(bm + row) * K + kc + ch * 8);
        }
#pragma unroll
        for (int it = 0; it < 4; it++) {
            int id = tid + it * 256;
            int row = id >> 2, ch = id & 3;
            uint32_t swz = (uint32_t)(row * 64 + ((ch ^ ((row >> 1) & 3)) << 4));
            cpasync16(smb + s*STAGE + AT*8192 + swz, bp + (size_t)(bn + row) * K + kc + ch * 8);
        }
        asm volatile("cp.async.commit_group;");
    };

#pragma unroll
    for (int s = 0; s < STAGES - 1; s++) load_stage(s, s * KT);

    const int wid = tid >> 5, lane = tid & 31;
    const int wm = wid & 1, wn = wid >> 1;

    float acc[4][8][4];
#pragma unroll
    for (int a = 0; a < 4; a++)
#pragma unroll
        for (int bb = 0; bb < 8; bb++)
#pragma unroll
            for (int c = 0; c < 4; c++) acc[a][bb][c] = 0.f;

    for (int i = 0; i < NC; i++) {
        asm volatile("cp.async.wait_group 1;");
        __syncthreads();

        if (i + STAGES - 1 < NC)
            load_stage((i + STAGES - 1) % STAGES, (i + STAGES - 1) * KT);
        else
            asm volatile("cp.async.commit_group;");

        const uint32_t stb = smb + (i % STAGES) * STAGE;
#pragma unroll
        for (int h = 0; h < 2; h++) {
            uint32_t ah[4][4], al[4][4];
            uint32_t bf[8][2];
#pragma unroll
            for (int tm = 0; tm < 4; tm++) {
                int row = wm*64 + tm*16 + (lane & 15);
                int ch  = 2*h + (lane >> 4);
                uint32_t ad = stb + row*64 + ((ch ^ ((row >> 1) & 3)) << 4);
                ldsm_x4(ah[tm], ad);
                if (AT == 2) ldsm_x4(al[tm], ad + 8192);
            }
#pragma unroll
            for (int tb = 0; tb < 4; tb++) {
                int row = wn*64 + tb*16 + ((lane >> 4) << 3) + (lane & 7);
                int ch  = 2*h + ((lane >> 3) & 1);
                uint32_t bd = stb + AT*8192 + row*64 + ((ch ^ ((row >> 1) & 3)) << 4);
                uint32_t r[4];
                ldsm_x4(r, bd);
                bf[tb*2][0] = r[0]; bf[tb*2][1] = r[1];
                bf[tb*2+1][0] = r[2]; bf[tb*2+1][1] = r[3];
            }
#pragma unroll
            for (int tm = 0; tm < 4; tm++)
#pragma unroll
                for (int tn = 0; tn < 8; tn++) {
                    mma_f16(acc[tm][tn], ah[tm], bf[tn][0], bf[tn][1]);
                    if (AT == 2)
                        mma_f16(acc[tm][tn], al[tm], bf[tn][0], bf[tn][1]);
                }
        }
    }

#pragma unroll
    for (int tm = 0; tm < 4; tm++) {
        int row = bm + wm*64 + tm*16 + (lane >> 2);
#pragma unroll
        for (int hf = 0; hf < 2; hf++) {
            int r = row + hf*8;
            float bv = bias ? bias[r] : 0.f;
            float* dst = C + (size_t)r * N + bn + wn*64 + (lane & 3)*2;
#pragma unroll
            for (int tn = 0; tn < 8; tn++) {
                float x0 = acc[tm][tn][hf*2+0] + bv;
                float x1 = acc[tm][tn][hf*2+1] + bv;
                if (act) {
                    x0 = x0 > 0.f ? x0 : expf(x0) - 1.f;
                    x1 = x1 > 0.f ? x1 : expf(x1) - 1.f;
                }
                *(float2*)(dst + tn*8) = make_float2(x0, x1);
            }
        }
    }
}

// ===================== stencil =====================
__global__ void __launch_bounds__(256) k_stencil9(const float* __restrict__ G,
                                                  float* __restrict__ out) {
    __shared__ float t3[3][64][64];
    int bid = blockIdx.x;
    int b = bid >> 12;
    int rest = bid & 4095;
    int ny = rest >> 6, py = rest & 63;
    const float* Gb = G + (size_t)b * NP * NP;
    float* ob = out + (size_t)b * NP * NP;
    int tid = threadIdx.x;

#pragma unroll
    for (int dy = 0; dy < 3; dy++) {
        int gy = ny + dy - 1, gpy = py + dy - 1;
        bool ok = (unsigned)gy < 64 && (unsigned)gpy < 64;
        for (int idx = tid; idx < 4096; idx += 256) {
            int i = idx >> 6, jj = idx & 63;
            t3[dy][i][jj] = ok ? Gb[((size_t)(gy*64 + i)) * NP + gpy*64 + jj] : 0.f;
        }
    }
    __syncthreads();

    int px = tid & 63;
    int nx0 = tid >> 6;
    for (int nx = nx0; nx < 64; nx += 4) {
        float s = 0.f;
#pragma unroll
        for (int dy = 0; dy < 3; dy++)
#pragma unroll
            for (int dx = -1; dx <= 1; dx++) {
                int a = nx + dx, c = px + dx;
                if ((unsigned)a < 64 && (unsigned)c < 64)
                    s += t3[dy][a][c];
            }
        ob[((size_t)(ny*64 + nx)) * NP + py*64 + px] = s * g_inv[b*NP + ny*64 + nx];
    }
}

// ===================== fuse1 + permutation =====================
__global__ void k_fuseperm(const float* __restrict__ in, float* __restrict__ out) {
    __shared__ float tile[64 * 65];
    int brow = blockIdx.x;
    int b = brow / NP, rp = brow % NP;
    int nx = rp >> 6, ny = rp & 63;
    int r = ny * 64 + nx;
    const float* src = in + (size_t)b * NP * NP;
    float*       dst = out + ((size_t)b * NP + rp) * NP;
    int tid = threadIdx.x;
    for (int k = tid; k < NP; k += 256) {
        float f = src[(size_t)r * NP + k];
        if (r > 0 && k > 0)           f += src[(size_t)(r-1) * NP + k - 1];
        if (r < NP-1 && k < NP-1)     f += src[(size_t)(r+1) * NP + k + 1];
        tile[(k & 63) * 65 + (k >> 6)] = f;
    }
    __syncthreads();
    for (int j = tid; j < NP; j += 256)
        dst[j] = tile[(j >> 6) * 65 + (j & 63)];
}

// ===================== softmax =====================
__global__ void k_smax1(const float* __restrict__ in) {
    int col = blockIdx.x * 256 + threadIdx.x;
    int chunk = blockIdx.y;
    int b = blockIdx.z;
    const float* base = in + (size_t)b * NP * NP;
    float mx = -1e30f, sm = 0.f;
    int r0 = chunk * 128;
    for (int r = r0; r < r0 + 128; r++) {
        float v = base[(size_t)r * NP + col];
        if (r > 0 && col > 0)         v += base[(size_t)(r-1) * NP + col - 1];
        if (r < NP-1 && col < NP-1)   v += base[(size_t)(r+1) * NP + col + 1];
        float l = v * (g_eq[r] * SCALEF);
        if (l > mx) { sm = sm * expf(mx - l) + 1.f; mx = l; }
        else        { sm += expf(l - mx); }
    }
    g_pmax[((size_t)b * 32 + chunk) * NP + col] = mx;
    g_psum[((size_t)b * 32 + chunk) * NP + col] = sm;
}

__global__ void k_smax2() {
    int idx = blockIdx.x * blockDim.x + threadIdx.x;
    if (idx >= BT * NP) return;
    int b = idx / NP, col = idx % NP;
    float M = -1e30f;
    for (int i = 0; i < 32; i++)
        M = fmaxf(M, g_pmax[((size_t)b * 32 + i) * NP + col]);
    float S = 0.f;
    for (int i = 0; i < 32; i++)
        S += g_psum[((size_t)b * 32 + i) * NP + col] *
             expf(g_pmax[((size_t)b * 32 + i) * NP + col] - M);
    g_cmax[idx] = M;
    g_csum[idx] = S;
}

__global__ void k_smax3T(const float* __restrict__ in) {
    __shared__ float raw[34][35];
    int b = blockIdx.z;
    int r0 = blockIdx.y * 32;
    int c0 = blockIdx.x * 32;
    int tid = threadIdx.x;
    const float* base = in + (size_t)b * NP * NP;
    for (int idx = tid; idx < 34*34; idx += 256) {
        int i = idx / 34, jj = idx % 34;
        int rr = r0 - 1 + i, cc = c0 - 1 + jj;
        raw[i][jj] = ((unsigned)rr < NP && (unsigned)cc < NP)
                   ? base[(size_t)rr * NP + cc] : 0.f;
    }
    __syncthreads();
    int tx = tid & 31, ty = tid >> 5;
#pragma unroll
    for (int k = 0; k < 4; k++) {
        int pl = ty + k * 8;
        int p = c0 + pl;
        int m = r0 + tx;
        float fused = raw[tx+1][pl+1] + raw[tx][pl] + raw[tx+2][pl+2];
        float eq = g_eq[m];
        float l = fused * (eq * SCALEF);
        float v = expf(l - g_cmax[b * NP + p]) / g_csum[b * NP + p] * eq;
        g_sT16[((size_t)b * NP + p) * NP + m] = __float2half(v);
    }
}

// ===================== gather + im2col =====================
__global__ void k_gather() {
    const int total = BT * CC * HWF;
    for (int idx = blockIdx.x * blockDim.x + threadIdx.x; idx < total;
         idx += gridDim.x * blockDim.x) {
        int X = idx & 127;
        int t = idx >> 7;
        int Y = t & 127; t >>= 7;
        int c = t & 127;
        int b = t >> 7;
        float acc = 0.f;
#pragma unroll
        for (int ki = 0; ki < 4; ki++) {
            int tyy = Y + 1 - ki;
            if (tyy < 0 || (tyy & 1)) continue;
            int yq = tyy >> 1;
            if (yq >= HS) continue;
#pragma unroll
            for (int kj = 0; kj < 4; kj++) {
                int txx = X + 1 - kj;
                if (txx < 0 || (txx & 1)) continue;
                int xq = txx >> 1;
                if (xq >= HS) continue;
                acc += g_yblk[((size_t)b * QQ + c * 16 + ki * 4 + kj) * NP + yq * HS + xq];
            }
        }
        g_y[idx] = acc * 0.25f;
    }
}

__global__ void k_im2col16(const float* __restrict__ src) {
    const size_t total = (size_t)BT * HWF * K1;
    const size_t stride = (size_t)gridDim.x * blockDim.x;
    for (size_t idx = (size_t)blockIdx.x * blockDim.x + threadIdx.x; idx < total; idx += stride) {
        int k = (int)(idx % K1);
        size_t t = idx / K1;
        int p = (int)(t & (HWF - 1));
        int b = (int)(t >> 14);
        int c = k / 9, kk = k % 9, ki = kk / 3, kj = kk % 3;
        int Y = p >> 7, X = p & 127;
        int y = Y + ki - 1, x = X + kj - 1;
        float v = 0.f;
        if ((unsigned)y < HH && (unsigned)x < WW)
            v = src[(((size_t)b * CC + c) * HH + y) * WW + x];
        g_col16[idx] = __float2half(v);
    }
}

// ===================== host orchestration =====================
extern "C" void kernel_launch(void* const* d_in, const int* in_sizes, int n_in,
                              void* d_out, int out_size) {
    const float* fg   = (const float*)d_in[0];
    const float* bg   = (const float*)d_in[1];
    const float* mask = (const float*)d_in[2];
    const float* w1   = (const float*)d_in[3];
    const float* b1   = (const float*)d_in[4];
    const float* w2   = (const float*)d_in[5];
    const float* b2   = (const float*)d_in[6];
    float* out = (float*)d_out;

    cudaFuncSetAttribute(mgemm, cudaFuncAttributeMaxDynamicSharedMemorySize, MGEMM_SMEM);
    cudaFuncSetAttribute(wgemm<1>, cudaFuncAttributeMaxDynamicSharedMemorySize, STAGES*(8192+16384));
    cudaFuncSetAttribute(wgemm<2>, cudaFuncAttributeMaxDynamicSharedMemorySize, STAGES*(16384+16384));

    __nv_bfloat16 *bh, *bl, *fh, *fl;
    __half *rt16, *st16, *col16, *w1h, *w1l, *w2h, *w2l;
    float *bufA, *bufB, *yblk, *yb, *hb;
    cudaGetSymbolAddress((void**)&bh, g_bh);     cudaGetSymbolAddress((void**)&bl, g_bl);
    cudaGetSymbolAddress((void**)&fh, g_fh);     cudaGetSymbolAddress((void**)&fl, g_fl);
    cudaGetSymbolAddress((void**)&rt16, g_rt16); cudaGetSymbolAddress((void**)&st16, g_sT16);
    cudaGetSymbolAddress((void**)&col16, g_col16);
    cudaGetSymbolAddress((void**)&w1h, g_w1h16); cudaGetSymbolAddress((void**)&w1l, g_w1l16);
    cudaGetSymbolAddress((void**)&w2h, g_w2h16); cudaGetSymbolAddress((void**)&w2l, g_w2l16);
    cudaGetSymbolAddress((void**)&bufA, g_bufA);
    cudaGetSymbolAddress((void**)&bufB, g_bufB);
    cudaGetSymbolAddress((void**)&yblk, g_yblk);
    cudaGetSymbolAddress((void**)&yb,   g_y);
    cudaGetSymbolAddress((void**)&hb,   g_h);

    // prep
    k_half   <<<(BT*NP*CC + 255)/256, 256>>>(bg, bh, bl);
    k_half   <<<(BT*NP*CC + 255)/256, 256>>>(fg, fh, fl);
    k_norm   <<<BT * NP, 128>>>(bg);
    k_rawTh  <<<8192, 256>>>(bg);
    k_eq     <<<16, 256>>>(mask);
    k_wsplit16<<<(CC*K1 + 255)/256, 256>>>(w1, w1h, w1l);
    k_wsplit16<<<(CC*K1 + 255)/256, 256>>>(w2, w2h, w2l);

    // GEMM1: G[u][v] = sum_c b[u][c] f[v][c]  (M=N=4096, K=128, bf16 3-term)
    mgemm<<<dim3(32, 32, BT), 256, MGEMM_SMEM>>>(
        bh, bl, fh, fl, bufA, CC, NP,
        (size_t)NP * CC, (size_t)NP * CC, (size_t)NP * NP);

    // scores = 9-tap diagonal stencil / norm
    k_stencil9<<<BT * 4096, 256>>>(bufA, bufB);

    // fuse1 + permutation
    k_fuseperm<<<BT * NP, 256>>>(bufB, bufA);

    // fuse2 on-the-fly + softmax
    k_smax1<<<dim3(16, 32, BT), 256>>>(bufA);
    k_smax2<<<32, 256>>>();
    k_smax3T<<<dim3(128, 128, BT), 256>>>(bufA);

    // GEMM2: yblk[q][p] = sum_m rt[q][m] * sT[p][m]  (fp16 single, 128x256)
    wgemm<1><<<dim3(16, 16, BT), 256, STAGES*(8192+16384)>>>(
        rt16, nullptr, st16, yblk, NP, NP,
        (size_t)QQ * NP, (size_t)NP * NP, (size_t)QQ * NP, nullptr, 0);

    k_gather<<<4096, 256>>>();

    // conv1 + ELU (fp16 weights 2-term x fp16 activations)
    k_im2col16<<<16384, 256>>>(yb);
    wgemm<2><<<dim3(HWF/256, 1, BT), 256, STAGES*(16384+16384)>>>(
        w1h, w1l, col16, hb, K1, HWF,
        (size_t)0, (size_t)HWF * K1, (size_t)CC * HWF, b1, 1);

    // conv2 + ELU
    k_im2col16<<<16384, 256>>>(hb);
    wgemm<2><<<dim3(HWF/256, 1, BT), 256, STAGES*(16384+16384)>>>(
        w2h, w2l, col16, out, K1, HWF,
        (size_t)0, (size_t)HWF * K1, (size_t)CC * HWF, b2, 1);
}

// round 7
// speedup vs baseline: 5.7214x; 1.1170x over previous
#include <cuda_runtime.h>
#include <cuda_bf16.h>
#include <cuda_fp16.h>
#include <math.h>
#include <stdint.h>

#define BT 2
#define CC 128
#define HH 128
#define WW 128
#define HS 64
#define NP 4096
#define K1 1152
#define QQ 2048
#define HWF 16384
#define SCALEF 10.0f

// ===================== scratch =====================
__device__ __align__(256) __nv_bfloat16 g_bh [(size_t)BT*NP*CC];
__device__ __align__(256) __nv_bfloat16 g_bl [(size_t)BT*NP*CC];
__device__ __align__(256) __nv_bfloat16 g_fh [(size_t)BT*NP*CC];
__device__ __align__(256) __nv_bfloat16 g_fl [(size_t)BT*NP*CC];
__device__ __align__(256) __half        g_rt16[(size_t)BT*QQ*NP];  // raw patches T [q=t*128+c][m]
__device__ __align__(256) __half        g_sT16[(size_t)BT*NP*NP];  // softmax T [p][m]
__device__ __align__(256) __half        g_y16 [(size_t)BT*HWF*CC]; // y image channels-last
__device__ __align__(256) __half        g_h16 [(size_t)BT*HWF*CC]; // h image channels-last
__device__ __align__(256) __half        g_w1h16[CC*K1], g_w1l16[CC*K1];
__device__ __align__(256) __half        g_w2h16[CC*K1], g_w2l16[CC*K1];
__device__ __align__(256) float g_bufA[(size_t)BT*NP*NP];
__device__ __align__(256) float g_bufB[(size_t)BT*NP*NP];
__device__ __align__(256) float g_yblkT[(size_t)BT*NP*QQ];         // [p][q] fp32
__device__ float g_eq  [NP];
__device__ float g_inv [BT*NP];
__device__ float g_pmax[BT*32*NP];
__device__ float g_psum[BT*32*NP];
__device__ float g_cmax[BT*NP];
__device__ float g_csum[BT*NP];

__device__ __forceinline__ void split_store(__nv_bfloat16* H, __nv_bfloat16* L,
                                            size_t idx, float v) {
    __nv_bfloat16 h = __float2bfloat16(v);
    H[idx] = h;
    L[idx] = __float2bfloat16(v - __bfloat162float(h));
}
__device__ __forceinline__ void split_store16(__half* H, __half* L, size_t idx, float v) {
    __half h = __float2half(v);
    H[idx] = h;
    L[idx] = __float2half(v - __half2float(h));
}
__device__ __forceinline__ uint32_t smem_u32(const void* p) {
    uint32_t a;
    asm("{ .reg .u64 t; cvta.to.shared.u64 t, %1; cvt.u32.u64 %0, t; }" : "=r"(a) : "l"(p));
    return a;
}
__device__ __forceinline__ void ldsm_x4(uint32_t (&r)[4], uint32_t addr) {
    asm volatile("ldmatrix.sync.aligned.m8n8.x4.shared.b16 {%0,%1,%2,%3}, [%4];"
                 : "=r"(r[0]), "=r"(r[1]), "=r"(r[2]), "=r"(r[3]) : "r"(addr));
}
__device__ __forceinline__ void mma_bf16(float (&d)[4], const uint32_t (&a)[4],
                                         uint32_t b0, uint32_t b1) {
    asm volatile("mma.sync.aligned.m16n8k16.row.col.f32.bf16.bf16.f32 "
        "{%0,%1,%2,%3}, {%4,%5,%6,%7}, {%8,%9}, {%0,%1,%2,%3};"
        : "+f"(d[0]), "+f"(d[1]), "+f"(d[2]), "+f"(d[3])
        : "r"(a[0]), "r"(a[1]), "r"(a[2]), "r"(a[3]), "r"(b0), "r"(b1));
}
__device__ __forceinline__ void mma_f16(float (&d)[4], const uint32_t (&a)[4],
                                        uint32_t b0, uint32_t b1) {
    asm volatile("mma.sync.aligned.m16n8k16.row.col.f32.f16.f16.f32 "
        "{%0,%1,%2,%3}, {%4,%5,%6,%7}, {%8,%9}, {%0,%1,%2,%3};"
        : "+f"(d[0]), "+f"(d[1]), "+f"(d[2]), "+f"(d[3])
        : "r"(a[0]), "r"(a[1]), "r"(a[2]), "r"(a[3]), "r"(b0), "r"(b1));
}
__device__ __forceinline__ void cpasync16(uint32_t saddr, const void* g) {
    asm volatile("cp.async.cg.shared.global [%0], [%1], 16;" :: "r"(saddr), "l"(g));
}
__device__ __forceinline__ void cpasync16z(uint32_t saddr, const void* g, int szbytes) {
    asm volatile("cp.async.cg.shared.global [%0], [%1], 16, %2;"
                 :: "r"(saddr), "l"(g), "r"(szbytes));
}

// ===================== prep =====================
__global__ void k_half(const float* __restrict__ src, __nv_bfloat16* H, __nv_bfloat16* L) {
    int idx = blockIdx.x * blockDim.x + threadIdx.x;
    if (idx >= BT * NP * CC) return;
    int c = idx & 127;
    int t = idx >> 7;
    int n = t & 4095;
    int b = t >> 12;
    int y = n >> 6, x = n & 63;
    float v = src[(((size_t)b*CC + c)*HH + 2*y)*WW + 2*x];
    split_store(H, L, (size_t)idx, v);
}

__global__ void k_norm(const float* __restrict__ bg) {
    int bn = blockIdx.x;
    int b = bn / NP, n = bn % NP;
    int ny = n / HS, nx = n % HS;
    int c = threadIdx.x;
    float ss = 0.f;
#pragma unroll
    for (int i = 0; i < 3; i++)
#pragma unroll
        for (int jj = 0; jj < 3; jj++) {
            int y = ny + i - 1, x = nx + jj - 1;
            if ((unsigned)y < HS && (unsigned)x < HS) {
                float v = bg[(((size_t)b*CC + c)*HH + 2*y)*WW + 2*x];
                ss += v * v;
            }
        }
    __shared__ float red[128];
    red[c] = ss;
    __syncthreads();
    for (int s = 64; s > 0; s >>= 1) {
        if (c < s) red[c] += red[c + s];
        __syncthreads();
    }
    if (c == 0)
        g_inv[bn] = 1.f / fmaxf(sqrtf(red[0]), 1e-4f);
}

// raw patches transposed with q = t*128 + c
__global__ void k_rawTh(const float* __restrict__ bg) {
    const size_t total = (size_t)BT * QQ * NP;
    const size_t stride = (size_t)gridDim.x * blockDim.x;
    for (size_t idx = (size_t)blockIdx.x * blockDim.x + threadIdx.x; idx < total; idx += stride) {
        int m = (int)(idx & (NP - 1));
        size_t tt2 = idx >> 12;
        int q = (int)(tt2 & (QQ - 1));
        int b = (int)(tt2 >> 11);
        int c = q & 127, t = q >> 7, di = t >> 2, dj = t & 3;
        int my = m >> 6, mx = m & 63;
        int Y = 2*my + di - 1, X = 2*mx + dj - 1;
        float v = 0.f;
        if ((unsigned)Y < HH && (unsigned)X < WW)
            v = bg[(((size_t)b*CC + c)*HH + Y)*WW + X];
        g_rt16[idx] = __float2half(v);
    }
}

__global__ void k_eq(const float* __restrict__ mask) {
    int n = blockIdx.x * blockDim.x + threadIdx.x;
    if (n >= NP) return;
    int ny = n / HS, nx = n % HS;
    float s = 0.f;
#pragma unroll
    for (int i = 0; i < 3; i++)
#pragma unroll
        for (int j = 0; j < 3; j++) {
            int y = ny + i - 1, x = nx + j - 1;
            if ((unsigned)y < HS && (unsigned)x < HS)
                s += mask[(2*y)*WW + 2*x];
        }
    g_eq[n] = ((s / 9.f) == 0.f) ? 1.f : 0.f;
}

// weight reorder: out[r][tap*128+c] = w[r][c*9+tap], fp16 hi/lo
__global__ void k_wreorder(const float* __restrict__ w, __half* H, __half* L) {
    int idx = blockIdx.x * blockDim.x + threadIdx.x;
    if (idx >= CC * K1) return;
    int r = idx / K1;
    int rem = idx % K1;
    int tap = rem >> 7;
    int c = rem & 127;
    split_store16(H, L, (size_t)idx, w[r * K1 + c * 9 + tap]);
}

// ===================== bf16-split GEMM (3-term, 128x128) — GEMM1 =============
#define KT 32
#define STAGES 3
#define STAGE_BYTES (4*128*KT*2)
#define MGEMM_SMEM (STAGES*STAGE_BYTES)

__global__ void __launch_bounds__(256, 1) mgemm(
    const __nv_bfloat16* __restrict__ Ah, const __nv_bfloat16* __restrict__ Al,
    const __nv_bfloat16* __restrict__ Bh, const __nv_bfloat16* __restrict__ Bl,
    float* __restrict__ C, int K, int N,
    size_t sA, size_t sB, size_t sC)
{
    extern __shared__ char sm[];
    const uint32_t smb = smem_u32(sm);
    const int tid = threadIdx.x;
    const int bz = blockIdx.z;
    const int bm = blockIdx.y * 128;
    const int bn = blockIdx.x * 128;
    C += sC * bz;

    const int j   = tid >> 6;
    const int l64 = tid & 63;
    const int rbase = (j < 2) ? bm : bn;
    const __nv_bfloat16* src =
        (j == 0) ? Ah + sA*bz : (j == 1) ? Al + sA*bz : (j == 2) ? Bh + sB*bz : Bl + sB*bz;

    const int NC = K >> 5;

#pragma unroll
    for (int s = 0; s < STAGES - 1; s++) {
        const int kc = s * KT;
#pragma unroll
        for (int i = 0; i < 8; i++) {
            int id = l64 + i * 64;
            int row = id >> 2, ch = id & 3;
            const void* g = src + (size_t)(rbase + row) * K + kc + ch * 8;
            uint32_t sa = smb + s*STAGE_BYTES + j*8192 + row*64 + ((ch ^ ((row >> 1) & 3)) << 4);
            cpasync16(sa, g);
        }
        asm volatile("cp.async.commit_group;");
    }

    const int wid = tid >> 5, lane = tid & 31;
    const int wm = wid & 1, wn = wid >> 1;

    float acc[4][4][4];
#pragma unroll
    for (int a = 0; a < 4; a++)
#pragma unroll
        for (int bb = 0; bb < 4; bb++)
#pragma unroll
            for (int c = 0; c < 4; c++) acc[a][bb][c] = 0.f;

    for (int i = 0; i < NC; i++) {
        asm volatile("cp.async.wait_group 1;");
        __syncthreads();

        if (i + STAGES - 1 < NC) {
            const int s2 = (i + STAGES - 1) % STAGES;
            const int kc = (i + STAGES - 1) * KT;
#pragma unroll
            for (int it = 0; it < 8; it++) {
                int id = l64 + it * 64;
                int row = id >> 2, ch = id & 3;
                const void* g = src + (size_t)(rbase + row) * K + kc + ch * 8;
                uint32_t sa = smb + s2*STAGE_BYTES + j*8192 + row*64 + ((ch ^ ((row >> 1) & 3)) << 4);
                cpasync16(sa, g);
            }
        }
        asm volatile("cp.async.commit_group;");

        const uint32_t stb = smb + (i % STAGES) * STAGE_BYTES;
#pragma unroll
        for (int h = 0; h < 2; h++) {
            uint32_t ah[4][4], al[4][4];
            uint32_t bh[4][2], bl[4][2];
#pragma unroll
            for (int tm = 0; tm < 4; tm++) {
                int row = wm*64 + tm*16 + (lane & 15);
                int ch  = 2*h + (lane >> 4);
                uint32_t ad = stb + row*64 + ((ch ^ ((row >> 1) & 3)) << 4);
                ldsm_x4(ah[tm], ad);
                ldsm_x4(al[tm], ad + 8192);
            }
#pragma unroll
            for (int tp = 0; tp < 2; tp++) {
                int row = wn*32 + tp*16 + ((lane >> 4) << 3) + (lane & 7);
                int ch  = 2*h + ((lane >> 3) & 1);
                uint32_t bd = stb + 16384 + row*64 + ((ch ^ ((row >> 1) & 3)) << 4);
                uint32_t r[4];
                ldsm_x4(r, bd);
                bh[tp*2][0] = r[0]; bh[tp*2][1] = r[1];
                bh[tp*2+1][0] = r[2]; bh[tp*2+1][1] = r[3];
                ldsm_x4(r, bd + 8192);
                bl[tp*2][0] = r[0]; bl[tp*2][1] = r[1];
                bl[tp*2+1][0] = r[2]; bl[tp*2+1][1] = r[3];
            }
#pragma unroll
            for (int tm = 0; tm < 4; tm++)
#pragma unroll
                for (int tn = 0; tn < 4; tn++) {
                    mma_bf16(acc[tm][tn], ah[tm], bh[tn][0], bh[tn][1]);
                    mma_bf16(acc[tm][tn], ah[tm], bl[tn][0], bl[tn][1]);
                    mma_bf16(acc[tm][tn], al[tm], bh[tn][0], bh[tn][1]);
                }
        }
    }

#pragma unroll
    for (int tm = 0; tm < 4; tm++) {
        int row = bm + wm*64 + tm*16 + (lane >> 2);
#pragma unroll
        for (int hf = 0; hf < 2; hf++) {
            int r = row + hf*8;
            float* dst = C + (size_t)r * N + bn + wn*32 + (lane & 3)*2;
#pragma unroll
            for (int tn = 0; tn < 4; tn++)
                *(float2*)(dst + tn*8) = make_float2(acc[tm][tn][hf*2+0], acc[tm][tn][hf*2+1]);
        }
    }
}

// ===================== fp16 wide GEMM: 128m x 256n (GEMM2) ===================
#define WSTAGE (8192 + 16384)
#define WGEMM_SMEM (STAGES*WSTAGE)

__global__ void __launch_bounds__(256, 1) wgemm(
    const __half* __restrict__ A0, const __half* __restrict__ B,
    float* __restrict__ C, int K, int N,
    size_t sA, size_t sB, size_t sC)
{
    extern __shared__ char sm[];
    const uint32_t smb = smem_u32(sm);
    const int tid = threadIdx.x;
    const int bz = blockIdx.z;
    const int bm = blockIdx.y * 128;
    const int bn = blockIdx.x * 256;
    C += sC * bz;
    const __half* a0 = A0 + sA * bz;
    const __half* bp = B + sB * bz;

    const int NC = K >> 5;

    auto load_stage = [&](int s, int kc) {
#pragma unroll
        for (int it = 0; it < 2; it++) {
            int id = tid + it * 256;
            int row = id >> 2, ch = id & 3;
            uint32_t swz = (uint32_t)(row * 64 + ((ch ^ ((row >> 1) & 3)) << 4));
            cpasync16(smb + s*WSTAGE + swz, a0 + (size_t)(bm + row) * K + kc + ch * 8);
        }
#pragma unroll
        for (int it = 0; it < 4; it++) {
            int id = tid + it * 256;
            int row = id >> 2, ch = id & 3;
            uint32_t swz = (uint32_t)(row * 64 + ((ch ^ ((row >> 1) & 3)) << 4));
            cpasync16(smb + s*WSTAGE + 8192 + swz, bp + (size_t)(bn + row) * K + kc + ch * 8);
        }
        asm volatile("cp.async.commit_group;");
    };

#pragma unroll
    for (int s = 0; s < STAGES - 1; s++) load_stage(s, s * KT);

    const int wid = tid >> 5, lane = tid & 31;
    const int wm = wid & 1, wn = wid >> 1;

    float acc[4][8][4];
#pragma unroll
    for (int a = 0; a < 4; a++)
#pragma unroll
        for (int bb = 0; bb < 8; bb++)
#pragma unroll
            for (int c = 0; c < 4; c++) acc[a][bb][c] = 0.f;

    for (int i = 0; i < NC; i++) {
        asm volatile("cp.async.wait_group 1;");
        __syncthreads();

        if (i + STAGES - 1 < NC)
            load_stage((i + STAGES - 1) % STAGES, (i + STAGES - 1) * KT);
        else
            asm volatile("cp.async.commit_group;");

        const uint32_t stb = smb + (i % STAGES) * WSTAGE;
#pragma unroll
        for (int h = 0; h < 2; h++) {
            uint32_t ah[4][4];
            uint32_t bf[8][2];
#pragma unroll
            for (int tm = 0; tm < 4; tm++) {
                int row = wm*64 + tm*16 + (lane & 15);
                int ch  = 2*h + (lane >> 4);
                uint32_t ad = stb + row*64 + ((ch ^ ((row >> 1) & 3)) << 4);
                ldsm_x4(ah[tm], ad);
            }
#pragma unroll
            for (int tb = 0; tb < 4; tb++) {
                int row = wn*64 + tb*16 + ((lane >> 4) << 3) + (lane & 7);
                int ch  = 2*h + ((lane >> 3) & 1);
                uint32_t bd = stb + 8192 + row*64 + ((ch ^ ((row >> 1) & 3)) << 4);
                uint32_t r[4];
                ldsm_x4(r, bd);
                bf[tb*2][0] = r[0]; bf[tb*2][1] = r[1];
                bf[tb*2+1][0] = r[2]; bf[tb*2+1][1] = r[3];
            }
#pragma unroll
            for (int tm = 0; tm < 4; tm++)
#pragma unroll
                for (int tn = 0; tn < 8; tn++)
                    mma_f16(acc[tm][tn], ah[tm], bf[tn][0], bf[tn][1]);
        }
    }

#pragma unroll
    for (int tm = 0; tm < 4; tm++) {
        int row = bm + wm*64 + tm*16 + (lane >> 2);
#pragma unroll
        for (int hf = 0; hf < 2; hf++) {
            int r = row + hf*8;
            float* dst = C + (size_t)r * N + bn + wn*64 + (lane & 3)*2;
#pragma unroll
            for (int tn = 0; tn < 8; tn++)
                *(float2*)(dst + tn*8) = make_float2(acc[tm][tn][hf*2+0], acc[tm][tn][hf*2+1]);
        }
    }
}

// ===================== implicit conv GEMM: 128ch x 256pix, fp16 2-term W =====
#define CSTAGE 32768
#define CGEMM_SMEM (STAGES*CSTAGE)
#define TPITCH 136

template<int OUT16>
__global__ void __launch_bounds__(256, 1) cgemm(
    const __half* __restrict__ Wh, const __half* __restrict__ Wl,
    const __half* __restrict__ img,     // [HWF][CC] fp16 channels-last, per-batch
    float* __restrict__ Cout, __half* __restrict__ out16,
    const float* __restrict__ bias)
{
    extern __shared__ char sm[];
    const uint32_t smb = smem_u32(sm);
    const int tid = threadIdx.x;
    const int bz = blockIdx.z;
    const int bn = blockIdx.x * 256;
    const __half* ib = img + (size_t)bz * HWF * CC;

    const int NC = K1 >> 5;   // 36

    auto load_stage = [&](int s, int kc) {
        // weights (hi/lo), 128 rows x 32 halves each
#pragma unroll
        for (int it = 0; it < 2; it++) {
            int id = tid + it * 256;
            int row = id >> 2, ch = id & 3;
            uint32_t swz = (uint32_t)(row * 64 + ((ch ^ ((row >> 1) & 3)) << 4));
            cpasync16(smb + s*CSTAGE + swz,        Wh + (size_t)row * K1 + kc + ch * 8);
            cpasync16(smb + s*CSTAGE + 8192 + swz, Wl + (size_t)row * K1 + kc + ch * 8);
        }
        // image: 256 pixels x 32 channels, tap fixed per chunk, zero-fill OOB
        int tap = kc >> 7;
        int ki = tap / 3, kj = tap - ki * 3;
        int c0 = kc & 127;
#pragma unroll
        for (int it = 0; it < 4; it++) {
            int id = tid + it * 256;
            int row = id >> 2, ch = id & 3;
            int p = bn + row;
            int Y = (p >> 7) + ki - 1, X = (p & 127) + kj - 1;
            bool ok = (unsigned)Y < HH && (unsigned)X < WW;
            const __half* g = ok ? ib + ((size_t)(Y * WW + X)) * CC + c0 + ch * 8 : ib;
            uint32_t swz = (uint32_t)(row * 64 + ((ch ^ ((row >> 1) & 3)) << 4));
            cpasync16z(smb + s*CSTAGE + 16384 + swz, g, ok ? 16 : 0);
        }
        asm volatile("cp.async.commit_group;");
    };

#pragma unroll
    for (int s = 0; s < STAGES - 1; s++) load_stage(s, s * KT);

    const int wid = tid >> 5, lane = tid & 31;
    const int wm = wid & 1, wn = wid >> 1;

    float acc[4][8][4];
#pragma unroll
    for (int a = 0; a < 4; a++)
#pragma unroll
        for (int bb = 0; bb < 8; bb++)
#pragma unroll
            for (int c = 0; c < 4; c++) acc[a][bb][c] = 0.f;

    for (int i = 0; i < NC; i++) {
        asm volatile("cp.async.wait_group 1;");
        __syncthreads();

        if (i + STAGES - 1 < NC)
            load_stage((i + STAGES - 1) % STAGES, (i + STAGES - 1) * KT);
        else
            asm volatile("cp.async.commit_group;");

        const uint32_t stb = smb + (i % STAGES) * CSTAGE;
#pragma unroll
        for (int h = 0; h < 2; h++) {
            uint32_t ah[4][4], al[4][4];
            uint32_t bf[8][2];
#pragma unroll
            for (int tm = 0; tm < 4; tm++) {
                int row = wm*64 + tm*16 + (lane & 15);
                int ch  = 2*h + (lane >> 4);
                uint32_t ad = stb + row*64 + ((ch ^ ((row >> 1) & 3)) << 4);
                ldsm_x4(ah[tm], ad);
                ldsm_x4(al[tm], ad + 8192);
            }
#pragma unroll
            for (int tb = 0; tb < 4; tb++) {
                int row = wn*64 + tb*16 + ((lane >> 4) << 3) + (lane & 7);
                int ch  = 2*h + ((lane >> 3) & 1);
                uint32_t bd = stb + 16384 + row*64 + ((ch ^ ((row >> 1) & 3)) << 4);
                uint32_t r[4];
                ldsm_x4(r, bd);
                bf[tb*2][0] = r[0]; bf[tb*2][1] = r[1];
                bf[tb*2+1][0] = r[2]; bf[tb*2+1][1] = r[3];
            }
#pragma unroll
            for (int tm = 0; tm < 4; tm++)
#pragma unroll
                for (int tn = 0; tn < 8; tn++) {
                    mma_f16(acc[tm][tn], ah[tm], bf[tn][0], bf[tn][1]);
                    mma_f16(acc[tm][tn], al[tm], bf[tn][0], bf[tn][1]);
                }
        }
    }

    if (OUT16) {
        // write channels-last fp16 image via smem transpose
        asm volatile("cp.async.wait_group 0;");
        __syncthreads();
        __half* st = (__half*)sm;
#pragma unroll
        for (int tm = 0; tm < 4; tm++) {
#pragma unroll
            for (int hf = 0; hf < 2; hf++) {
                int r = wm*64 + tm*16 + (lane >> 2) + hf*8;
                float bv = bias[r];
#pragma unroll
                for (int tn = 0; tn < 8; tn++) {
                    int col = wn*64 + tn*8 + (lane & 3)*2;
                    float x0 = acc[tm][tn][hf*2+0] + bv;
                    float x1 = acc[tm][tn][hf*2+1] + bv;
                    x0 = x0 > 0.f ? x0 : expf(x0) - 1.f;
                    x1 = x1 > 0.f ? x1 : expf(x1) - 1.f;
                    st[(size_t)col * TPITCH + r]       = __float2half(x0);
                    st[(size_t)(col+1) * TPITCH + r]   = __float2half(x1);
                }
            }
        }
        __syncthreads();
        __half* dst = out16 + ((size_t)bz * HWF + bn + tid) * CC;
        const uint4* srcv = (const uint4*)(st + (size_t)tid * TPITCH);
#pragma unroll
        for (int i = 0; i < 16; i++)
            ((uint4*)dst)[i] = srcv[i];
    } else {
        float* C = Cout + (size_t)bz * CC * HWF;
#pragma unroll
        for (int tm = 0; tm < 4; tm++) {
            int row = wm*64 + tm*16 + (lane >> 2);
#pragma unroll
            for (int hf = 0; hf < 2; hf++) {
                int r = row + hf*8;
                float bv = bias[r];
                float* dst = C + (size_t)r * HWF + bn + wn*64 + (lane & 3)*2;
#pragma unroll
                for (int tn = 0; tn < 8; tn++) {
                    float x0 = acc[tm][tn][hf*2+0] + bv;
                    float x1 = acc[tm][tn][hf*2+1] + bv;
                    x0 = x0 > 0.f ? x0 : expf(x0) - 1.f;
                    x1 = x1 > 0.f ? x1 : expf(x1) - 1.f;
                    *(float2*)(dst + tn*8) = make_float2(x0, x1);
                }
            }
        }
    }
}

// ===================== stencil =====================
__global__ void __launch_bounds__(256) k_stencil9(const float* __restrict__ G,
                                                  float* __restrict__ out) {
    __shared__ float t3[3][64][64];
    int bid = blockIdx.x;
    int b = bid >> 12;
    int rest = bid & 4095;
    int ny = rest >> 6, py = rest & 63;
    const float* Gb = G + (size_t)b * NP * NP;
    float* ob = out + (size_t)b * NP * NP;
    int tid = threadIdx.x;

#pragma unroll
    for (int dy = 0; dy < 3; dy++) {
        int gy = ny + dy - 1, gpy = py + dy - 1;
        bool ok = (unsigned)gy < 64 && (unsigned)gpy < 64;
        for (int idx = tid; idx < 4096; idx += 256) {
            int i = idx >> 6, jj = idx & 63;
            t3[dy][i][jj] = ok ? Gb[((size_t)(gy*64 + i)) * NP + gpy*64 + jj] : 0.f;
        }
    }
    __syncthreads();

    int px = tid & 63;
    int nx0 = tid >> 6;
    for (int nx = nx0; nx < 64; nx += 4) {
        float s = 0.f;
#pragma unroll
        for (int dy = 0; dy < 3; dy++)
#pragma unroll
            for (int dx = -1; dx <= 1; dx++) {
                int a = nx + dx, c = px + dx;
                if ((unsigned)a < 64 && (unsigned)c < 64)
                    s += t3[dy][a][c];
            }
        ob[((size_t)(ny*64 + nx)) * NP + py*64 + px] = s * g_inv[b*NP + ny*64 + nx];
    }
}

// ===================== fuse1 + permutation =====================
__global__ void k_fuseperm(const float* __restrict__ in, float* __restrict__ out) {
    __shared__ float tile[64 * 65];
    int brow = blockIdx.x;
    int b = brow / NP, rp = brow % NP;
    int nx = rp >> 6, ny = rp & 63;
    int r = ny * 64 + nx;
    const float* src = in + (size_t)b * NP * NP;
    float*       dst = out + ((size_t)b * NP + rp) * NP;
    int tid = threadIdx.x;
    for (int k = tid; k < NP; k += 256) {
        float f = src[(size_t)r * NP + k];
        if (r > 0 && k > 0)           f += src[(size_t)(r-1) * NP + k - 1];
        if (r < NP-1 && k < NP-1)     f += src[(size_t)(r+1) * NP + k + 1];
        tile[(k & 63) * 65 + (k >> 6)] = f;
    }
    __syncthreads();
    for (int j = tid; j < NP; j += 256)
        dst[j] = tile[(j >> 6) * 65 + (j & 63)];
}

// ===================== softmax (fuse2 on the fly) =====================
__global__ void k_smax1(const float* __restrict__ in) {
    int col = blockIdx.x * 256 + threadIdx.x;
    int chunk = blockIdx.y;
    int b = blockIdx.z;
    int lane = threadIdx.x & 31;
    const float* base = in + (size_t)b * NP * NP;
    int r0 = chunk * 128;

    float pm1 = (r0 > 0) ? base[(size_t)(r0-1) * NP + col] : 0.f;
    float p0  = base[(size_t)r0 * NP + col];
    float pp1 = (r0 + 1 < NP) ? base[(size_t)(r0+1) * NP + col] : 0.f;

    float mx = -1e30f, sm = 0.f;
    for (int r = r0; r < r0 + 128; r++) {
        float um1 = __shfl_up_sync(0xffffffffu, pm1, 1);
        if (lane == 0)
            um1 = (r > 0 && col > 0) ? base[(size_t)(r-1) * NP + col - 1] : 0.f;
        float dp1 = __shfl_down_sync(0xffffffffu, pp1, 1);
        if (lane == 31)
            dp1 = (r < NP-1 && col < NP-1) ? base[(size_t)(r+1) * NP + col + 1] : 0.f;
        float v = p0 + um1 + dp1;
        float l = v * (g_eq[r] * SCALEF);
        if (l > mx) { sm = sm * expf(mx - l) + 1.f; mx = l; }
        else        { sm += expf(l - mx); }
        pm1 = p0; p0 = pp1;
        pp1 = (r + 2 < NP) ? base[(size_t)(r+2) * NP + col] : 0.f;
    }
    g_pmax[((size_t)b * 32 + chunk) * NP + col] = mx;
    g_psum[((size_t)b * 32 + chunk) * NP + col] = sm;
}

__global__ void k_smax2() {
    int idx = blockIdx.x * blockDim.x + threadIdx.x;
    if (idx >= BT * NP) return;
    int b = idx / NP, col = idx % NP;
    float M = -1e30f;
    for (int i = 0; i < 32; i++)
        M = fmaxf(M, g_pmax[((size_t)b * 32 + i) * NP + col]);
    float S = 0.f;
    for (int i = 0; i < 32; i++)
        S += g_psum[((size_t)b * 32 + i) * NP + col] *
             expf(g_pmax[((size_t)b * 32 + i) * NP + col] - M);
    g_cmax[idx] = M;
    g_csum[idx] = S;
}

__global__ void k_smax3T(const float* __restrict__ in) {
    __shared__ float raw[34][35];
    int b = blockIdx.z;
    int r0 = blockIdx.y * 32;
    int c0 = blockIdx.x * 32;
    int tid = threadIdx.x;
    const float* base = in + (size_t)b * NP * NP;
    for (int idx = tid; idx < 34*34; idx += 256) {
        int i = idx / 34, jj = idx % 34;
        int rr = r0 - 1 + i, cc = c0 - 1 + jj;
        raw[i][jj] = ((unsigned)rr < NP && (unsigned)cc < NP)
                   ? base[(size_t)rr * NP + cc] : 0.f;
    }
    __syncthreads();
    int tx = tid & 31, ty = tid >> 5;
#pragma unroll
    for (int k = 0; k < 4; k++) {
        int pl = ty + k * 8;
        int p = c0 + pl;
        int m = r0 + tx;
        float fused = raw[tx+1][pl+1] + raw[tx][pl] + raw[tx+2][pl+2];
        float eq = g_eq[m];
        float l = fused * (eq * SCALEF);
        float v = expf(l - g_cmax[b * NP + p]) / g_csum[b * NP + p] * eq;
        g_sT16[((size_t)b * NP + p) * NP + m] = __float2half(v);
    }
}

// ===================== gather: yblkT -> channels-last fp16 image ============
__global__ void k_gather16() {
    int wid = threadIdx.x >> 5, lane = threadIdx.x & 31;
    int p = blockIdx.x * 8 + wid;
    int b = blockIdx.y;
    int Y = p >> 7, X = p & 127;
    const float* yb = g_yblkT + (size_t)b * NP * QQ;
    float4 acc = make_float4(0.f, 0.f, 0.f, 0.f);
#pragma unroll
    for (int di = 0; di < 4; di++) {
        int ty = Y + 1 - di;
        if (ty < 0 || (ty & 1)) continue;
        int my = ty >> 1;
        if (my >= HS) continue;
#pragma unroll
        for (int dj = 0; dj < 4; dj++) {
            int tx = X + 1 - dj;
            if (tx < 0 || (tx & 1)) continue;
            int mx = tx >> 1;
            if (mx >= HS) continue;
            int m = my * 64 + mx, t = di * 4 + dj;
            float4 v = *(const float4*)(yb + (size_t)m * QQ + t * 128 + lane * 4);
            acc.x += v.x; acc.y += v.y; acc.z += v.z; acc.w += v.w;
        }
    }
    union { __half2 h[2]; uint2 u; } cv;
    cv.h[0] = __floats2half2_rn(acc.x * 0.25f, acc.y * 0.25f);
    cv.h[1] = __floats2half2_rn(acc.z * 0.25f, acc.w * 0.25f);
    *(uint2*)(g_y16 + ((size_t)b * HWF + p) * CC + lane * 4) = cv.u;
}

// ===================== host orchestration =====================
extern "C" void kernel_launch(void* const* d_in, const int* in_sizes, int n_in,
                              void* d_out, int out_size) {
    const float* fg   = (const float*)d_in[0];
    const float* bg   = (const float*)d_in[1];
    const float* mask = (const float*)d_in[2];
    const float* w1   = (const float*)d_in[3];
    const float* b1   = (const float*)d_in[4];
    const float* w2   = (const float*)d_in[5];
    const float* b2   = (const float*)d_in[6];
    float* out = (float*)d_out;

    cudaFuncSetAttribute(mgemm, cudaFuncAttributeMaxDynamicSharedMemorySize, MGEMM_SMEM);
    cudaFuncSetAttribute(wgemm, cudaFuncAttributeMaxDynamicSharedMemorySize, WGEMM_SMEM);
    cudaFuncSetAttribute(cgemm<0>, cudaFuncAttributeMaxDynamicSharedMemorySize, CGEMM_SMEM);
    cudaFuncSetAttribute(cgemm<1>, cudaFuncAttributeMaxDynamicSharedMemorySize, CGEMM_SMEM);

    __nv_bfloat16 *bh, *bl, *fh, *fl;
    __half *rt16, *st16, *y16, *h16, *w1h, *w1l, *w2h, *w2l;
    float *bufA, *bufB, *yblkT;
    cudaGetSymbolAddress((void**)&bh, g_bh);     cudaGetSymbolAddress((void**)&bl, g_bl);
    cudaGetSymbolAddress((void**)&fh, g_fh);     cudaGetSymbolAddress((void**)&fl, g_fl);
    cudaGetSymbolAddress((void**)&rt16, g_rt16); cudaGetSymbolAddress((void**)&st16, g_sT16);
    cudaGetSymbolAddress((void**)&y16, g_y16);   cudaGetSymbolAddress((void**)&h16, g_h16);
    cudaGetSymbolAddress((void**)&w1h, g_w1h16); cudaGetSymbolAddress((void**)&w1l, g_w1l16);
    cudaGetSymbolAddress((void**)&w2h, g_w2h16); cudaGetSymbolAddress((void**)&w2l, g_w2l16);
    cudaGetSymbolAddress((void**)&bufA, g_bufA);
    cudaGetSymbolAddress((void**)&bufB, g_bufB);
    cudaGetSymbolAddress((void**)&yblkT, g_yblkT);

    // prep
    k_half    <<<(BT*NP*CC + 255)/256, 256>>>(bg, bh, bl);
    k_half    <<<(BT*NP*CC + 255)/256, 256>>>(fg, fh, fl);
    k_norm    <<<BT * NP, 128>>>(bg);
    k_rawTh   <<<8192, 256>>>(bg);
    k_eq      <<<16, 256>>>(mask);
    k_wreorder<<<(CC*K1 + 255)/256, 256>>>(w1, w1h, w1l);
    k_wreorder<<<(CC*K1 + 255)/256, 256>>>(w2, w2h, w2l);

    // GEMM1: G[u][v] = sum_c b[u][c] f[v][c]  (bf16 3-term)
    mgemm<<<dim3(32, 32, BT), 256, MGEMM_SMEM>>>(
        bh, bl, fh, fl, bufA, CC, NP,
        (size_t)NP * CC, (size_t)NP * CC, (size_t)NP * NP);

    // scores = 9-tap diagonal stencil / norm
    k_stencil9<<<BT * 4096, 256>>>(bufA, bufB);

    // fuse1 + permutation
    k_fuseperm<<<BT * NP, 256>>>(bufB, bufA);

    // fuse2 on-the-fly + softmax
    k_smax1<<<dim3(16, 32, BT), 256>>>(bufA);
    k_smax2<<<32, 256>>>();
    k_smax3T<<<dim3(128, 128, BT), 256>>>(bufA);

    // GEMM2 (transposed): yblkT[p][q] = sum_m sT[p][m] * rt[q][m]
    wgemm<<<dim3(QQ/256, NP/128, BT), 256, WGEMM_SMEM>>>(
        st16, rt16, yblkT, NP, QQ,
        (size_t)NP * NP, (size_t)QQ * NP, (size_t)NP * QQ);

    // transposed-conv gather -> channels-last fp16 y image
    k_gather16<<<dim3(HWF/8, BT), 256>>>();

    // conv1 + ELU (implicit, fp16 2-term W) -> h16 image
    cgemm<1><<<dim3(HWF/256, 1, BT), 256, CGEMM_SMEM>>>(
        w1h, w1l, y16, nullptr, h16, b1);

    // conv2 + ELU (implicit) -> out fp32 NCHW
    cgemm<0><<<dim3(HWF/256, 1, BT), 256, CGEMM_SMEM>>>(
        w2h, w2l, h16, out, nullptr, b2);
}